// round 3
// baseline (speedup 1.0000x reference)
#include <cuda_runtime.h>
#include <math.h>

// Problem constants
constexpr int Bc  = 2;
constexpr int Tt  = 2048;
constexpr int Dd  = 2048;
constexpr int NH  = 16;   // query heads
constexpr int KHn = 8;    // kv heads
constexpr int HD  = 128;  // head dim
constexpr int FF  = 8192; // ffw dim
constexpr int Mtot = Bc * Tt;      // 4096
constexpr int GG  = NH / KHn;      // 2

// -------- scratch (static device globals; no allocations) --------
__device__ float g_xn  [(size_t)Mtot * Dd];
__device__ float g_q   [(size_t)Mtot * NH * HD];
__device__ float g_k   [(size_t)Mtot * KHn * HD];
__device__ float g_v   [(size_t)Mtot * KHn * HD];
__device__ float g_enc [(size_t)Mtot * NH * HD];
__device__ float g_res [(size_t)Mtot * Dd];
__device__ float g_h   [(size_t)Mtot * Dd];
__device__ float g_gate[(size_t)Mtot * FF];
__device__ float g_up  [(size_t)Mtot * FF];

// ---------------- RMSNorm ----------------
__global__ void rmsnorm_kernel(const float* __restrict__ x,
                               const float* __restrict__ scale,
                               float* __restrict__ out) {
    int row = blockIdx.x;
    const float* xr = x + (size_t)row * Dd;
    float ss = 0.f;
    for (int i = threadIdx.x; i < Dd; i += blockDim.x) {
        float v = xr[i];
        ss += v * v;
    }
    __shared__ float red[32];
    #pragma unroll
    for (int o = 16; o; o >>= 1) ss += __shfl_xor_sync(0xffffffffu, ss, o);
    if ((threadIdx.x & 31) == 0) red[threadIdx.x >> 5] = ss;
    __syncthreads();
    if (threadIdx.x < 32) {
        float v = (threadIdx.x < (blockDim.x >> 5)) ? red[threadIdx.x] : 0.f;
        #pragma unroll
        for (int o = 16; o; o >>= 1) v += __shfl_xor_sync(0xffffffffu, v, o);
        if (threadIdx.x == 0) red[0] = v;
    }
    __syncthreads();
    float inv = rsqrtf(red[0] / (float)Dd + 1e-6f);
    float* outr = out + (size_t)row * Dd;
    for (int i = threadIdx.x; i < Dd; i += blockDim.x)
        outr[i] = xr[i] * inv * (1.f + scale[i]);
}

// ---------------- Generic fp32 GEMM: C = A[M,Kd] @ B[Kd,Ncols] (+resid) ----
// Tiles 128x128, Ktile 8, 256 threads, 8x8 microtile.
// grid.z = head index; B += z*bHeadStride, C (and nothing else) shifted by z*cHeadOff cols.
// Assumes M%128==0, Ncols%128==0 (per tile mapping), Kd%8==0 -- true for all uses here.
constexpr int TM = 128, TN = 128, TK = 8;

__global__ __launch_bounds__(256) void gemm_kernel(
    const float* __restrict__ A, const float* __restrict__ Bm,
    const float* __restrict__ resid, float* __restrict__ C,
    int Kd, int ldb, int ldc,
    long long bHeadStride, int cHeadOff) {

    Bm += (size_t)blockIdx.z * (size_t)bHeadStride;
    C  += (size_t)blockIdx.z * (size_t)cHeadOff;

    __shared__ float As[TK][TM];
    __shared__ float Bs[TK][TN];

    int m0 = blockIdx.y * TM, n0 = blockIdx.x * TN;
    int tid = threadIdx.x;
    int arow = tid >> 1, acol = (tid & 1) * 4;   // A tile 128x8
    int brow = tid >> 5, bcol = (tid & 31) * 4;  // B tile 8x128
    int tx = tid & 15, ty = tid >> 4;            // micro tile coords

    float acc[8][8];
    #pragma unroll
    for (int i = 0; i < 8; i++)
        #pragma unroll
        for (int j = 0; j < 8; j++) acc[i][j] = 0.f;

    for (int k0 = 0; k0 < Kd; k0 += TK) {
        float4 av = *(const float4*)&A[(size_t)(m0 + arow) * Kd + k0 + acol];
        As[acol + 0][arow] = av.x;
        As[acol + 1][arow] = av.y;
        As[acol + 2][arow] = av.z;
        As[acol + 3][arow] = av.w;
        float4 bv = *(const float4*)&Bm[(size_t)(k0 + brow) * ldb + n0 + bcol];
        *(float4*)&Bs[brow][bcol] = bv;
        __syncthreads();
        #pragma unroll
        for (int kk = 0; kk < TK; kk++) {
            float af[8], bf[8];
            *(float4*)&af[0] = *(const float4*)&As[kk][ty * 8];
            *(float4*)&af[4] = *(const float4*)&As[kk][ty * 8 + 4];
            *(float4*)&bf[0] = *(const float4*)&Bs[kk][tx * 8];
            *(float4*)&bf[4] = *(const float4*)&Bs[kk][tx * 8 + 4];
            #pragma unroll
            for (int i = 0; i < 8; i++)
                #pragma unroll
                for (int j = 0; j < 8; j++)
                    acc[i][j] += af[i] * bf[j];
        }
        __syncthreads();
    }

    #pragma unroll
    for (int i = 0; i < 8; i++) {
        int m = m0 + ty * 8 + i;
        float* crow = C + (size_t)m * ldc + n0 + tx * 8;
        #pragma unroll
        for (int j = 0; j < 8; j += 4) {
            float4 v;
            v.x = acc[i][j]; v.y = acc[i][j + 1];
            v.z = acc[i][j + 2]; v.w = acc[i][j + 3];
            if (resid) {
                const float4 r = *(const float4*)&resid[(size_t)m * ldc + n0 + tx * 8 + j];
                v.x += r.x; v.y += r.y; v.z += r.z; v.w += r.w;
            }
            *(float4*)&crow[j] = v;
        }
    }
}

// ---------------- RoPE (in place) ----------------
__global__ void rope_kernel(float* __restrict__ x, const int* __restrict__ positions,
                            int heads, float outscale) {
    int row = blockIdx.x;   // b*T + t
    int h   = blockIdx.y;
    int i   = threadIdx.x;  // 0..63
    float pos = (float)positions[row];
    float ts = powf(10000.f, (float)i / 64.f);
    float ang = pos / ts;
    float s, c;
    sincosf(ang, &s, &c);
    float* p = x + ((size_t)row * heads + h) * HD;
    float x1 = p[i], x2 = p[i + 64];
    p[i]      = (x1 * c - x2 * s) * outscale;
    p[i + 64] = (x2 * c + x1 * s) * outscale;
}

// ---------------- Flash attention (causal, online softmax) ----------------
constexpr int BQ = 16;
constexpr int BK = 128;
constexpr int STP = 20; // score-row pad (float4-aligned, low bank conflict)

extern __shared__ float fa_smem[];

__global__ __launch_bounds__(128) void flash_kernel(
    const float* __restrict__ q, const float* __restrict__ k,
    const float* __restrict__ v, float* __restrict__ enc) {

    int tq0 = blockIdx.x * BQ;
    int n   = blockIdx.y;
    int b   = blockIdx.z;
    int kvh = n / GG;
    int tid = threadIdx.x;

    float* Qt   = fa_smem;               // [HD][BQ]   (transposed)
    float* Ks   = Qt + HD * BQ;          // [BK][HD+1]
    float* Vs   = Ks + BK * (HD + 1);    // [BK][HD+1]
    float* St   = Vs + BK * (HD + 1);    // [BK][STP]  (transposed scores/probs)
    float* m_sm = St + BK * STP;         // [BQ]
    float* l_sm = m_sm + BQ;             // [BQ]
    float* a_sm = l_sm + BQ;             // [BQ]

    // Load Q tile transposed: Qt[d*BQ + qi]
    for (int idx = tid; idx < BQ * HD; idx += 128) {
        int d = idx >> 4, qi = idx & 15;
        Qt[idx] = q[(((size_t)b * Tt + tq0 + qi) * NH + n) * HD + d];
    }
    if (tid < BQ) { m_sm[tid] = -1e30f; l_sm[tid] = 0.f; }

    float o[BQ];
    #pragma unroll
    for (int i = 0; i < BQ; i++) o[i] = 0.f;

    int ntiles = (tq0 + BQ + BK - 1) / BK;
    for (int kt = 0; kt < ntiles; kt++) {
        int s0 = kt * BK;
        __syncthreads();
        // stage K,V
        for (int idx = tid; idx < BK * HD; idx += 128) {
            int j = idx >> 7, d = idx & 127;
            size_t g = (((size_t)b * Tt + s0 + j) * KHn + kvh) * HD + d;
            Ks[j * (HD + 1) + d] = k[g];
            Vs[j * (HD + 1) + d] = v[g];
        }
        __syncthreads();

        // scores: thread tid handles key j = tid
        int j = tid;
        int s = s0 + j;
        float sc[BQ];
        #pragma unroll
        for (int qi = 0; qi < BQ; qi++) sc[qi] = 0.f;
        #pragma unroll 4
        for (int d = 0; d < HD; d++) {
            float kv_ = Ks[j * (HD + 1) + d];
            float qv[16];
            *(float4*)&qv[0]  = *(const float4*)&Qt[d * BQ + 0];
            *(float4*)&qv[4]  = *(const float4*)&Qt[d * BQ + 4];
            *(float4*)&qv[8]  = *(const float4*)&Qt[d * BQ + 8];
            *(float4*)&qv[12] = *(const float4*)&Qt[d * BQ + 12];
            #pragma unroll
            for (int qi = 0; qi < BQ; qi++) sc[qi] += qv[qi] * kv_;
        }
        // causal mask
        #pragma unroll
        for (int qi = 0; qi < BQ; qi++)
            if (s > tq0 + qi) sc[qi] = -1e30f;

        // publish scores for row-max
        #pragma unroll
        for (int qi = 0; qi < BQ; qi++) St[j * STP + qi] = sc[qi];
        __syncthreads();

        if (tid < BQ) {
            float mold = m_sm[tid];
            float rowmax = -1e30f;
            for (int jj = 0; jj < BK; jj++)
                rowmax = fmaxf(rowmax, St[jj * STP + tid]);
            float mnew = fmaxf(mold, rowmax);
            a_sm[tid] = __expf(mold - mnew);
            m_sm[tid] = mnew;
        }
        __syncthreads();

        // probs
        #pragma unroll
        for (int qi = 0; qi < BQ; qi++) {
            float p = __expf(sc[qi] - m_sm[qi]);
            St[j * STP + qi] = p;
        }
        __syncthreads();

        if (tid < BQ) {
            float rs = 0.f;
            for (int jj = 0; jj < BK; jj++) rs += St[jj * STP + tid];
            l_sm[tid] = l_sm[tid] * a_sm[tid] + rs;
        }

        // o update: thread tid = dim d
        float al[BQ];
        #pragma unroll
        for (int qi = 0; qi < BQ; qi++) { al[qi] = a_sm[qi]; o[qi] *= al[qi]; }
        #pragma unroll 4
        for (int jj = 0; jj < BK; jj++) {
            float vv = Vs[jj * (HD + 1) + tid];
            float pv[16];
            *(float4*)&pv[0]  = *(const float4*)&St[jj * STP + 0];
            *(float4*)&pv[4]  = *(const float4*)&St[jj * STP + 4];
            *(float4*)&pv[8]  = *(const float4*)&St[jj * STP + 8];
            *(float4*)&pv[12] = *(const float4*)&St[jj * STP + 12];
            #pragma unroll
            for (int qi = 0; qi < BQ; qi++) o[qi] += pv[qi] * vv;
        }
    }
    __syncthreads();
    #pragma unroll
    for (int qi = 0; qi < BQ; qi++)
        enc[(((size_t)b * Tt + tq0 + qi) * NH + n) * HD + tid] = o[qi] / l_sm[qi];
}

// ---------------- gelu(gate)*up ----------------
__global__ void gelu_mul_kernel(const float* __restrict__ gate,
                                const float* __restrict__ up,
                                float* __restrict__ out) {
    size_t i = (size_t)blockIdx.x * blockDim.x + threadIdx.x;
    float g = gate[i];
    float t = tanhf(0.7978845608028654f * (g + 0.044715f * g * g * g));
    out[i] = 0.5f * g * (1.f + t) * up[i];
}

// ---------------- launch ----------------
extern "C" void kernel_launch(void* const* d_in, const int* in_sizes, int n_in,
                              void* d_out, int out_size) {
    const float* x        = (const float*)d_in[0];
    const int*   pos      = (const int*)  d_in[1];
    // d_in[2] attn_mask: causal, recomputed in-kernel
    const float* w_q      = (const float*)d_in[3];
    const float* w_kv     = (const float*)d_in[4];
    const float* w_av     = (const float*)d_in[5];
    const float* s_attn   = (const float*)d_in[6];
    const float* s_ffw    = (const float*)d_in[7];
    const float* w_gating = (const float*)d_in[8];
    const float* w_linear = (const float*)d_in[9];
    float* out = (float*)d_out;

    float *xn, *qp, *kp, *vp, *encp, *resp, *hp, *gatep, *upp;
    cudaGetSymbolAddress((void**)&xn,    g_xn);
    cudaGetSymbolAddress((void**)&qp,    g_q);
    cudaGetSymbolAddress((void**)&kp,    g_k);
    cudaGetSymbolAddress((void**)&vp,    g_v);
    cudaGetSymbolAddress((void**)&encp,  g_enc);
    cudaGetSymbolAddress((void**)&resp,  g_res);
    cudaGetSymbolAddress((void**)&hp,    g_h);
    cudaGetSymbolAddress((void**)&gatep, g_gate);
    cudaGetSymbolAddress((void**)&upp,   g_up);

    // 1. pre-attn rmsnorm
    rmsnorm_kernel<<<Mtot, 256>>>(x, s_attn, xn);

    // 2. projections (per-head GEMMs)
    dim3 gq(1, Mtot / TM, NH);
    gemm_kernel<<<gq, 256>>>(xn, w_q, nullptr, qp, Dd, HD, NH * HD,
                             (long long)Dd * HD, HD);
    dim3 gk(1, Mtot / TM, KHn);
    gemm_kernel<<<gk, 256>>>(xn, w_kv, nullptr, kp, Dd, HD, KHn * HD,
                             (long long)Dd * HD, HD);
    gemm_kernel<<<gk, 256>>>(xn, w_kv + (size_t)KHn * Dd * HD, nullptr, vp,
                             Dd, HD, KHn * HD, (long long)Dd * HD, HD);

    // 3. rope
    rope_kernel<<<dim3(Mtot, NH), 64>>>(qp, pos, NH, 0.08838834764831845f); // H^-0.5
    rope_kernel<<<dim3(Mtot, KHn), 64>>>(kp, pos, KHn, 1.f);

    // 4. flash attention
    int fa_smem_bytes = (HD * BQ + 2 * BK * (HD + 1) + BK * STP + 3 * BQ) * (int)sizeof(float);
    cudaFuncSetAttribute(flash_kernel, cudaFuncAttributeMaxDynamicSharedMemorySize, fa_smem_bytes);
    flash_kernel<<<dim3(Tt / BQ, NH, Bc), 128, fa_smem_bytes>>>(qp, kp, vp, encp);

    // 5. attn output proj + residual
    dim3 gav(Dd / TN, Mtot / TM, 1);
    gemm_kernel<<<gav, 256>>>(encp, w_av, x, resp, NH * HD, Dd, Dd, 0, 0);

    // 6. pre-ffw rmsnorm
    rmsnorm_kernel<<<Mtot, 256>>>(resp, s_ffw, hp);

    // 7. gate / up GEMMs
    dim3 gff(FF / TN, Mtot / TM, 1);
    gemm_kernel<<<gff, 256>>>(hp, w_gating, nullptr, gatep, Dd, FF, FF, 0, 0);
    gemm_kernel<<<gff, 256>>>(hp, w_gating + (size_t)Dd * FF, nullptr, upp, Dd, FF, FF, 0, 0);

    // 8. act = gelu(gate) * up (in place into gate buffer)
    gelu_mul_kernel<<<((size_t)Mtot * FF) / 256, 256>>>(gatep, upp, gatep);

    // 9. down proj + residual -> out
    dim3 gout(Dd / TN, Mtot / TM, 1);
    gemm_kernel<<<gout, 256>>>(gatep, w_linear, resp, out, FF, Dd, Dd, 0, 0);
}

// round 4
// speedup vs baseline: 3.2948x; 3.2948x over previous
#include <cuda_runtime.h>
#include <math.h>
#include <stdint.h>

// Problem constants
constexpr int Bc  = 2;
constexpr int Tt  = 2048;
constexpr int Dd  = 2048;
constexpr int NH  = 16;   // query heads
constexpr int KHn = 8;    // kv heads
constexpr int HD  = 128;  // head dim
constexpr int FF  = 8192; // ffw dim
constexpr int Mtot = Bc * Tt;      // 4096
constexpr int GG  = NH / KHn;      // 2

// -------- scratch (static device globals; no allocations) --------
__device__ float g_xn  [(size_t)Mtot * Dd];
__device__ float g_q   [(size_t)Mtot * NH * HD];
__device__ float g_k   [(size_t)Mtot * KHn * HD];
__device__ float g_v   [(size_t)Mtot * KHn * HD];
__device__ float g_enc [(size_t)Mtot * NH * HD];
__device__ float g_res [(size_t)Mtot * Dd];
__device__ float g_h   [(size_t)Mtot * Dd];
__device__ float g_gate[(size_t)Mtot * FF];
__device__ float g_up  [(size_t)Mtot * FF];

// ---------------- RMSNorm ----------------
__global__ void rmsnorm_kernel(const float* __restrict__ x,
                               const float* __restrict__ scale,
                               float* __restrict__ out) {
    int row = blockIdx.x;
    const float* xr = x + (size_t)row * Dd;
    float ss = 0.f;
    for (int i = threadIdx.x; i < Dd; i += blockDim.x) {
        float v = xr[i];
        ss += v * v;
    }
    __shared__ float red[32];
    #pragma unroll
    for (int o = 16; o; o >>= 1) ss += __shfl_xor_sync(0xffffffffu, ss, o);
    if ((threadIdx.x & 31) == 0) red[threadIdx.x >> 5] = ss;
    __syncthreads();
    if (threadIdx.x < 32) {
        float v = (threadIdx.x < (blockDim.x >> 5)) ? red[threadIdx.x] : 0.f;
        #pragma unroll
        for (int o = 16; o; o >>= 1) v += __shfl_xor_sync(0xffffffffu, v, o);
        if (threadIdx.x == 0) red[0] = v;
    }
    __syncthreads();
    float inv = rsqrtf(red[0] / (float)Dd + 1e-6f);
    float* outr = out + (size_t)row * Dd;
    for (int i = threadIdx.x; i < Dd; i += blockDim.x)
        outr[i] = xr[i] * inv * (1.f + scale[i]);
}

// ---------------- TF32 tensor-core GEMM ----------------
// C[M,N] = A[M,Kd] @ B[Kd,N] (+resid), fp32 in/out, tf32 (rna) mma, fp32 accum.
// Tile: BM=128, BN=128, BK=32. 256 threads = 8 warps (2x4), warp tile 64x32.
// mma.sync.aligned.m16n8k8.row.col.f32.tf32.tf32.f32
constexpr int BM = 128, BN = 128, BK = 32;
constexpr int APAD = 4;  // As stride 36: fragment bank = lane (conflict-free)
constexpr int BPAD = 8;  // Bs stride 136: fragment bank = 8*tig+grp (conflict-free)

__device__ __forceinline__ uint32_t f2tf32(float f) {
    uint32_t r;
    asm("cvt.rna.tf32.f32 %0, %1;" : "=r"(r) : "f"(f));
    return r;
}

__device__ __forceinline__ void mma_tf32(float& c0, float& c1, float& c2, float& c3,
                                         uint32_t a0, uint32_t a1, uint32_t a2, uint32_t a3,
                                         uint32_t b0, uint32_t b1) {
    asm volatile(
        "mma.sync.aligned.m16n8k8.row.col.f32.tf32.tf32.f32 "
        "{%0,%1,%2,%3}, {%4,%5,%6,%7}, {%8,%9}, {%0,%1,%2,%3};"
        : "+f"(c0), "+f"(c1), "+f"(c2), "+f"(c3)
        : "r"(a0), "r"(a1), "r"(a2), "r"(a3), "r"(b0), "r"(b1));
}

__global__ __launch_bounds__(256) void gemm_tc_kernel(
    const float* __restrict__ A, const float* __restrict__ Bm,
    const float* __restrict__ resid, float* __restrict__ C,
    int Kd, int ldb, int ldc,
    long long bHeadStride, int cHeadOff) {

    Bm += (size_t)blockIdx.z * (size_t)bHeadStride;
    C  += (size_t)blockIdx.z * (size_t)cHeadOff;

    __shared__ uint32_t As[BM][BK + APAD];   // tf32 bit patterns
    __shared__ uint32_t Bs[BK][BN + BPAD];

    int m0 = blockIdx.y * BM, n0 = blockIdx.x * BN;
    int tid  = threadIdx.x;
    int lane = tid & 31, warp = tid >> 5;
    int grp = lane >> 2, tig = lane & 3;
    int wm = (warp >> 2) * 64;   // warp M offset (0 or 64)
    int wn = (warp & 3) * 32;    // warp N offset (0,32,64,96)

    // global load mapping
    int ar  = tid >> 3;            // 0..31  (A row base; rows ar+32*i)
    int ac4 = (tid & 7) * 4;       // A col (k) within tile
    int bkr = tid >> 5;            // 0..7   (B k row base; rows bkr+8*i)
    int bc4 = (tid & 31) * 4;      // B col (n) within tile

    float acc[4][4][4];
    #pragma unroll
    for (int mt = 0; mt < 4; mt++)
        #pragma unroll
        for (int nt = 0; nt < 4; nt++)
            #pragma unroll
            for (int r = 0; r < 4; r++) acc[mt][nt][r] = 0.f;

    for (int k0 = 0; k0 < Kd; k0 += BK) {
        // stage A (128 x 32)
        #pragma unroll
        for (int i = 0; i < 4; i++) {
            int m = ar + 32 * i;
            float4 av = *(const float4*)&A[(size_t)(m0 + m) * Kd + k0 + ac4];
            As[m][ac4 + 0] = f2tf32(av.x);
            As[m][ac4 + 1] = f2tf32(av.y);
            As[m][ac4 + 2] = f2tf32(av.z);
            As[m][ac4 + 3] = f2tf32(av.w);
        }
        // stage B (32 x 128)
        #pragma unroll
        for (int i = 0; i < 4; i++) {
            int kr = bkr + 8 * i;
            float4 bv = *(const float4*)&Bm[(size_t)(k0 + kr) * ldb + n0 + bc4];
            Bs[kr][bc4 + 0] = f2tf32(bv.x);
            Bs[kr][bc4 + 1] = f2tf32(bv.y);
            Bs[kr][bc4 + 2] = f2tf32(bv.z);
            Bs[kr][bc4 + 3] = f2tf32(bv.w);
        }
        __syncthreads();

        #pragma unroll
        for (int kk = 0; kk < 4; kk++) {
            int k = kk * 8;
            uint32_t af[4][4], bf[4][2];
            #pragma unroll
            for (int mt = 0; mt < 4; mt++) {
                int row = wm + mt * 16 + grp;
                af[mt][0] = As[row    ][k + tig];
                af[mt][1] = As[row + 8][k + tig];
                af[mt][2] = As[row    ][k + tig + 4];
                af[mt][3] = As[row + 8][k + tig + 4];
            }
            #pragma unroll
            for (int nt = 0; nt < 4; nt++) {
                int col = wn + nt * 8 + grp;
                bf[nt][0] = Bs[k + tig    ][col];
                bf[nt][1] = Bs[k + tig + 4][col];
            }
            #pragma unroll
            for (int mt = 0; mt < 4; mt++)
                #pragma unroll
                for (int nt = 0; nt < 4; nt++)
                    mma_tf32(acc[mt][nt][0], acc[mt][nt][1], acc[mt][nt][2], acc[mt][nt][3],
                             af[mt][0], af[mt][1], af[mt][2], af[mt][3],
                             bf[nt][0], bf[nt][1]);
        }
        __syncthreads();
    }

    // epilogue: c0,c1 at (m, n),(m, n+1); c2,c3 at (m+8, n),(m+8, n+1)
    #pragma unroll
    for (int mt = 0; mt < 4; mt++) {
        #pragma unroll
        for (int nt = 0; nt < 4; nt++) {
            int m = m0 + wm + mt * 16 + grp;
            int n = n0 + wn + nt * 8 + 2 * tig;
            float2 v0 = make_float2(acc[mt][nt][0], acc[mt][nt][1]);
            float2 v1 = make_float2(acc[mt][nt][2], acc[mt][nt][3]);
            if (resid) {
                float2 r0 = *(const float2*)&resid[(size_t)m * ldc + n];
                float2 r1 = *(const float2*)&resid[(size_t)(m + 8) * ldc + n];
                v0.x += r0.x; v0.y += r0.y;
                v1.x += r1.x; v1.y += r1.y;
            }
            *(float2*)&C[(size_t)m * ldc + n]       = v0;
            *(float2*)&C[(size_t)(m + 8) * ldc + n] = v1;
        }
    }
}

// ---------------- RoPE (in place) ----------------
__global__ void rope_kernel(float* __restrict__ x, const int* __restrict__ positions,
                            int heads, float outscale) {
    int row = blockIdx.x;   // b*T + t
    int h   = blockIdx.y;
    int i   = threadIdx.x;  // 0..63
    float pos = (float)positions[row];
    float ts = powf(10000.f, (float)i / 64.f);
    float ang = pos / ts;
    float s, c;
    sincosf(ang, &s, &c);
    float* p = x + ((size_t)row * heads + h) * HD;
    float x1 = p[i], x2 = p[i + 64];
    p[i]      = (x1 * c - x2 * s) * outscale;
    p[i + 64] = (x2 * c + x1 * s) * outscale;
}

// ---------------- Flash attention (causal, online softmax) ----------------
constexpr int BQ = 16;
constexpr int BKfa = 128;
constexpr int STP = 20; // score-row pad (float4-aligned, low bank conflict)

extern __shared__ float fa_smem[];

__global__ __launch_bounds__(128) void flash_kernel(
    const float* __restrict__ q, const float* __restrict__ k,
    const float* __restrict__ v, float* __restrict__ enc) {

    int tq0 = blockIdx.x * BQ;
    int n   = blockIdx.y;
    int b   = blockIdx.z;
    int kvh = n / GG;
    int tid = threadIdx.x;

    float* Qt   = fa_smem;                 // [HD][BQ]   (transposed)
    float* Ks   = Qt + HD * BQ;            // [BKfa][HD+1]
    float* Vs   = Ks + BKfa * (HD + 1);    // [BKfa][HD+1]
    float* St   = Vs + BKfa * (HD + 1);    // [BKfa][STP]  (transposed scores/probs)
    float* m_sm = St + BKfa * STP;         // [BQ]
    float* l_sm = m_sm + BQ;               // [BQ]
    float* a_sm = l_sm + BQ;               // [BQ]

    for (int idx = tid; idx < BQ * HD; idx += 128) {
        int d = idx >> 4, qi = idx & 15;
        Qt[idx] = q[(((size_t)b * Tt + tq0 + qi) * NH + n) * HD + d];
    }
    if (tid < BQ) { m_sm[tid] = -1e30f; l_sm[tid] = 0.f; }

    float o[BQ];
    #pragma unroll
    for (int i = 0; i < BQ; i++) o[i] = 0.f;

    int ntiles = (tq0 + BQ + BKfa - 1) / BKfa;
    for (int kt = 0; kt < ntiles; kt++) {
        int s0 = kt * BKfa;
        __syncthreads();
        for (int idx = tid; idx < BKfa * HD; idx += 128) {
            int j = idx >> 7, d = idx & 127;
            size_t g = (((size_t)b * Tt + s0 + j) * KHn + kvh) * HD + d;
            Ks[j * (HD + 1) + d] = k[g];
            Vs[j * (HD + 1) + d] = v[g];
        }
        __syncthreads();

        int j = tid;
        int s = s0 + j;
        float sc[BQ];
        #pragma unroll
        for (int qi = 0; qi < BQ; qi++) sc[qi] = 0.f;
        #pragma unroll 4
        for (int d = 0; d < HD; d++) {
            float kv_ = Ks[j * (HD + 1) + d];
            float qv[16];
            *(float4*)&qv[0]  = *(const float4*)&Qt[d * BQ + 0];
            *(float4*)&qv[4]  = *(const float4*)&Qt[d * BQ + 4];
            *(float4*)&qv[8]  = *(const float4*)&Qt[d * BQ + 8];
            *(float4*)&qv[12] = *(const float4*)&Qt[d * BQ + 12];
            #pragma unroll
            for (int qi = 0; qi < BQ; qi++) sc[qi] += qv[qi] * kv_;
        }
        #pragma unroll
        for (int qi = 0; qi < BQ; qi++)
            if (s > tq0 + qi) sc[qi] = -1e30f;

        #pragma unroll
        for (int qi = 0; qi < BQ; qi++) St[j * STP + qi] = sc[qi];
        __syncthreads();

        if (tid < BQ) {
            float mold = m_sm[tid];
            float rowmax = -1e30f;
            for (int jj = 0; jj < BKfa; jj++)
                rowmax = fmaxf(rowmax, St[jj * STP + tid]);
            float mnew = fmaxf(mold, rowmax);
            a_sm[tid] = __expf(mold - mnew);
            m_sm[tid] = mnew;
        }
        __syncthreads();

        #pragma unroll
        for (int qi = 0; qi < BQ; qi++) {
            float p = __expf(sc[qi] - m_sm[qi]);
            St[j * STP + qi] = p;
        }
        __syncthreads();

        if (tid < BQ) {
            float rs = 0.f;
            for (int jj = 0; jj < BKfa; jj++) rs += St[jj * STP + tid];
            l_sm[tid] = l_sm[tid] * a_sm[tid] + rs;
        }

        float al[BQ];
        #pragma unroll
        for (int qi = 0; qi < BQ; qi++) { al[qi] = a_sm[qi]; o[qi] *= al[qi]; }
        #pragma unroll 4
        for (int jj = 0; jj < BKfa; jj++) {
            float vv = Vs[jj * (HD + 1) + tid];
            float pv[16];
            *(float4*)&pv[0]  = *(const float4*)&St[jj * STP + 0];
            *(float4*)&pv[4]  = *(const float4*)&St[jj * STP + 4];
            *(float4*)&pv[8]  = *(const float4*)&St[jj * STP + 8];
            *(float4*)&pv[12] = *(const float4*)&St[jj * STP + 12];
            #pragma unroll
            for (int qi = 0; qi < BQ; qi++) o[qi] += pv[qi] * vv;
        }
    }
    __syncthreads();
    #pragma unroll
    for (int qi = 0; qi < BQ; qi++)
        enc[(((size_t)b * Tt + tq0 + qi) * NH + n) * HD + tid] = o[qi] / l_sm[qi];
}

// ---------------- gelu(gate)*up ----------------
__global__ void gelu_mul_kernel(const float* __restrict__ gate,
                                const float* __restrict__ up,
                                float* __restrict__ out) {
    size_t i = (size_t)blockIdx.x * blockDim.x + threadIdx.x;
    float g = gate[i];
    float t = tanhf(0.7978845608028654f * (g + 0.044715f * g * g * g));
    out[i] = 0.5f * g * (1.f + t) * up[i];
}

// ---------------- launch ----------------
extern "C" void kernel_launch(void* const* d_in, const int* in_sizes, int n_in,
                              void* d_out, int out_size) {
    const float* x        = (const float*)d_in[0];
    const int*   pos      = (const int*)  d_in[1];
    // d_in[2] attn_mask: causal, recomputed in-kernel
    const float* w_q      = (const float*)d_in[3];
    const float* w_kv     = (const float*)d_in[4];
    const float* w_av     = (const float*)d_in[5];
    const float* s_attn   = (const float*)d_in[6];
    const float* s_ffw    = (const float*)d_in[7];
    const float* w_gating = (const float*)d_in[8];
    const float* w_linear = (const float*)d_in[9];
    float* out = (float*)d_out;

    float *xn, *qp, *kp, *vp, *encp, *resp, *hp, *gatep, *upp;
    cudaGetSymbolAddress((void**)&xn,    g_xn);
    cudaGetSymbolAddress((void**)&qp,    g_q);
    cudaGetSymbolAddress((void**)&kp,    g_k);
    cudaGetSymbolAddress((void**)&vp,    g_v);
    cudaGetSymbolAddress((void**)&encp,  g_enc);
    cudaGetSymbolAddress((void**)&resp,  g_res);
    cudaGetSymbolAddress((void**)&hp,    g_h);
    cudaGetSymbolAddress((void**)&gatep, g_gate);
    cudaGetSymbolAddress((void**)&upp,   g_up);

    // 1. pre-attn rmsnorm
    rmsnorm_kernel<<<Mtot, 256>>>(x, s_attn, xn);

    // 2. projections (per-head tensor-core GEMMs)
    dim3 gq(1, Mtot / BM, NH);
    gemm_tc_kernel<<<gq, 256>>>(xn, w_q, nullptr, qp, Dd, HD, NH * HD,
                                (long long)Dd * HD, HD);
    dim3 gk(1, Mtot / BM, KHn);
    gemm_tc_kernel<<<gk, 256>>>(xn, w_kv, nullptr, kp, Dd, HD, KHn * HD,
                                (long long)Dd * HD, HD);
    gemm_tc_kernel<<<gk, 256>>>(xn, w_kv + (size_t)KHn * Dd * HD, nullptr, vp,
                                Dd, HD, KHn * HD, (long long)Dd * HD, HD);

    // 3. rope
    rope_kernel<<<dim3(Mtot, NH), 64>>>(qp, pos, NH, 0.08838834764831845f); // H^-0.5
    rope_kernel<<<dim3(Mtot, KHn), 64>>>(kp, pos, KHn, 1.f);

    // 4. flash attention
    int fa_smem_bytes = (HD * BQ + 2 * BKfa * (HD + 1) + BKfa * STP + 3 * BQ) * (int)sizeof(float);
    cudaFuncSetAttribute(flash_kernel, cudaFuncAttributeMaxDynamicSharedMemorySize, fa_smem_bytes);
    flash_kernel<<<dim3(Tt / BQ, NH, Bc), 128, fa_smem_bytes>>>(qp, kp, vp, encp);

    // 5. attn output proj + residual
    dim3 gav(Dd / BN, Mtot / BM, 1);
    gemm_tc_kernel<<<gav, 256>>>(encp, w_av, x, resp, NH * HD, Dd, Dd, 0, 0);

    // 6. pre-ffw rmsnorm
    rmsnorm_kernel<<<Mtot, 256>>>(resp, s_ffw, hp);

    // 7. gate / up GEMMs
    dim3 gff(FF / BN, Mtot / BM, 1);
    gemm_tc_kernel<<<gff, 256>>>(hp, w_gating, nullptr, gatep, Dd, FF, FF, 0, 0);
    gemm_tc_kernel<<<gff, 256>>>(hp, w_gating + (size_t)Dd * FF, nullptr, upp, Dd, FF, FF, 0, 0);

    // 8. act = gelu(gate) * up (in place into gate buffer)
    gelu_mul_kernel<<<((size_t)Mtot * FF) / 256, 256>>>(gatep, upp, gatep);

    // 9. down proj + residual -> out
    dim3 gout(Dd / BN, Mtot / BM, 1);
    gemm_tc_kernel<<<gout, 256>>>(gatep, w_linear, resp, out, FF, Dd, Dd, 0, 0);
}

// round 5
// speedup vs baseline: 3.5420x; 1.0750x over previous
#include <cuda_runtime.h>
#include <math.h>
#include <stdint.h>

// Problem constants
constexpr int Bc  = 2;
constexpr int Tt  = 2048;
constexpr int Dd  = 2048;
constexpr int NH  = 16;   // query heads
constexpr int KHn = 8;    // kv heads
constexpr int HD  = 128;  // head dim
constexpr int FF  = 8192; // ffw dim
constexpr int Mtot = Bc * Tt;      // 4096
constexpr int GG  = NH / KHn;      // 2

// -------- scratch (static device globals; no allocations) --------
__device__ float g_xn  [(size_t)Mtot * Dd];
__device__ float g_q   [(size_t)Mtot * NH * HD];
__device__ float g_k   [(size_t)Mtot * KHn * HD];
__device__ float g_v   [(size_t)Mtot * KHn * HD];
__device__ float g_enc [(size_t)Mtot * NH * HD];
__device__ float g_res [(size_t)Mtot * Dd];
__device__ float g_h   [(size_t)Mtot * Dd];
__device__ float g_gate[(size_t)Mtot * FF];

// ---------------- RMSNorm ----------------
__global__ void rmsnorm_kernel(const float* __restrict__ x,
                               const float* __restrict__ scale,
                               float* __restrict__ out) {
    int row = blockIdx.x;
    const float* xr = x + (size_t)row * Dd;
    float ss = 0.f;
    for (int i = threadIdx.x; i < Dd; i += blockDim.x) {
        float v = xr[i];
        ss += v * v;
    }
    __shared__ float red[32];
    #pragma unroll
    for (int o = 16; o; o >>= 1) ss += __shfl_xor_sync(0xffffffffu, ss, o);
    if ((threadIdx.x & 31) == 0) red[threadIdx.x >> 5] = ss;
    __syncthreads();
    if (threadIdx.x < 32) {
        float v = (threadIdx.x < (blockDim.x >> 5)) ? red[threadIdx.x] : 0.f;
        #pragma unroll
        for (int o = 16; o; o >>= 1) v += __shfl_xor_sync(0xffffffffu, v, o);
        if (threadIdx.x == 0) red[0] = v;
    }
    __syncthreads();
    float inv = rsqrtf(red[0] / (float)Dd + 1e-6f);
    float* outr = out + (size_t)row * Dd;
    for (int i = threadIdx.x; i < Dd; i += blockDim.x)
        outr[i] = xr[i] * inv * (1.f + scale[i]);
}

// ---------------- TF32 tensor-core GEMM (double-buffered pipeline) --------
// C[M,N] = A[M,Kd] @ B[Kd,N] (+resid / gelu-gate epilogue).
// Tile: BM=128, BN=128, BK=32. 256 threads = 8 warps (2x4), warp tile 64x32.
constexpr int BM = 128, BN = 128, BK = 32;
constexpr int ASTR = BK + 4;   // 36: fragment bank = lane (conflict-free)
constexpr int BSTR = BN + 8;   // 136: conflict-free + 16B aligned rows

__device__ __forceinline__ uint32_t f2tf32(float f) {
    uint32_t r;
    asm("cvt.rna.tf32.f32 %0, %1;" : "=r"(r) : "f"(f));
    return r;
}

__device__ __forceinline__ void mma_tf32(float& c0, float& c1, float& c2, float& c3,
                                         uint32_t a0, uint32_t a1, uint32_t a2, uint32_t a3,
                                         uint32_t b0, uint32_t b1) {
    asm volatile(
        "mma.sync.aligned.m16n8k8.row.col.f32.tf32.tf32.f32 "
        "{%0,%1,%2,%3}, {%4,%5,%6,%7}, {%8,%9}, {%0,%1,%2,%3};"
        : "+f"(c0), "+f"(c1), "+f"(c2), "+f"(c3)
        : "r"(a0), "r"(a1), "r"(a2), "r"(a3), "r"(b0), "r"(b1));
}

__device__ __forceinline__ void cp_async16(uint32_t smem_addr, const void* gptr) {
    asm volatile("cp.async.cg.shared.global [%0], [%1], 16;" :: "r"(smem_addr), "l"(gptr));
}

extern __shared__ float dynsmem[];

__global__ __launch_bounds__(256, 2) void gemm_tc_kernel(
    const float* __restrict__ A, const float* __restrict__ Bm,
    const float* __restrict__ resid, const float* __restrict__ gelu_src,
    float* __restrict__ C,
    int Kd, int ldb, int ldc,
    long long bHeadStride, int cHeadOff) {

    Bm += (size_t)blockIdx.z * (size_t)bHeadStride;
    C  += (size_t)blockIdx.z * (size_t)cHeadOff;

    uint32_t* AsU = (uint32_t*)dynsmem;                    // [2][BM][ASTR] tf32
    float*    BsF = dynsmem + 2 * BM * ASTR;               // [2][BK][BSTR] fp32

    int m0 = blockIdx.y * BM, n0 = blockIdx.x * BN;
    int tid  = threadIdx.x;
    int lane = tid & 31, warp = tid >> 5;
    int grp = lane >> 2, tig = lane & 3;
    int wm = (warp >> 2) * 64;
    int wn = (warp & 3) * 32;

    int ar  = tid >> 3;            // A row base (rows ar+32*i)
    int ac4 = (tid & 7) * 4;       // A k-col
    int bkr = tid >> 5;            // B k-row base (rows bkr+8*i)
    int bc4 = (tid & 31) * 4;      // B n-col

    float acc[4][4][4];
    #pragma unroll
    for (int mt = 0; mt < 4; mt++)
        #pragma unroll
        for (int nt = 0; nt < 4; nt++)
            #pragma unroll
            for (int r = 0; r < 4; r++) acc[mt][nt][r] = 0.f;

    int ntile = Kd / BK;
    float4 avA[4];

    // ---- prologue: tile 0 ----
    #pragma unroll
    for (int i = 0; i < 4; i++)
        avA[i] = *(const float4*)&A[(size_t)(m0 + ar + 32 * i) * Kd + ac4];
    #pragma unroll
    for (int i = 0; i < 4; i++) {
        int kr = bkr + 8 * i;
        uint32_t sa = (uint32_t)__cvta_generic_to_shared(&BsF[(size_t)kr * BSTR + bc4]);
        cp_async16(sa, &Bm[(size_t)kr * ldb + n0 + bc4]);
    }
    asm volatile("cp.async.commit_group;");
    #pragma unroll
    for (int i = 0; i < 4; i++) {
        int m = ar + 32 * i;
        AsU[(size_t)m * ASTR + ac4 + 0] = f2tf32(avA[i].x);
        AsU[(size_t)m * ASTR + ac4 + 1] = f2tf32(avA[i].y);
        AsU[(size_t)m * ASTR + ac4 + 2] = f2tf32(avA[i].z);
        AsU[(size_t)m * ASTR + ac4 + 3] = f2tf32(avA[i].w);
    }
    asm volatile("cp.async.wait_group 0;");
    __syncthreads();

    for (int t = 0; t < ntile; t++) {
        int cur = t & 1, nxt = cur ^ 1;
        const uint32_t* Asb = AsU + (size_t)cur * BM * ASTR;
        const float*    Bsb = BsF + (size_t)cur * BK * BSTR;

        if (t + 1 < ntile) {
            int k0n = (t + 1) * BK;
            #pragma unroll
            for (int i = 0; i < 4; i++)
                avA[i] = *(const float4*)&A[(size_t)(m0 + ar + 32 * i) * Kd + k0n + ac4];
            float* Bsn = BsF + (size_t)nxt * BK * BSTR;
            #pragma unroll
            for (int i = 0; i < 4; i++) {
                int kr = bkr + 8 * i;
                uint32_t sa = (uint32_t)__cvta_generic_to_shared(&Bsn[(size_t)kr * BSTR + bc4]);
                cp_async16(sa, &Bm[(size_t)(k0n + kr) * ldb + n0 + bc4]);
            }
            asm volatile("cp.async.commit_group;");
        }

        #pragma unroll
        for (int kk = 0; kk < 4; kk++) {
            int k = kk * 8;
            uint32_t af[4][4], bf[4][2];
            #pragma unroll
            for (int mt = 0; mt < 4; mt++) {
                int row = wm + mt * 16 + grp;
                af[mt][0] = Asb[(size_t)(row    ) * ASTR + k + tig];
                af[mt][1] = Asb[(size_t)(row + 8) * ASTR + k + tig];
                af[mt][2] = Asb[(size_t)(row    ) * ASTR + k + tig + 4];
                af[mt][3] = Asb[(size_t)(row + 8) * ASTR + k + tig + 4];
            }
            #pragma unroll
            for (int nt = 0; nt < 4; nt++) {
                int col = wn + nt * 8 + grp;
                bf[nt][0] = f2tf32(Bsb[(size_t)(k + tig    ) * BSTR + col]);
                bf[nt][1] = f2tf32(Bsb[(size_t)(k + tig + 4) * BSTR + col]);
            }
            #pragma unroll
            for (int mt = 0; mt < 4; mt++)
                #pragma unroll
                for (int nt = 0; nt < 4; nt++)
                    mma_tf32(acc[mt][nt][0], acc[mt][nt][1], acc[mt][nt][2], acc[mt][nt][3],
                             af[mt][0], af[mt][1], af[mt][2], af[mt][3],
                             bf[nt][0], bf[nt][1]);
        }

        if (t + 1 < ntile) {
            uint32_t* Asn = AsU + (size_t)nxt * BM * ASTR;
            #pragma unroll
            for (int i = 0; i < 4; i++) {
                int m = ar + 32 * i;
                Asn[(size_t)m * ASTR + ac4 + 0] = f2tf32(avA[i].x);
                Asn[(size_t)m * ASTR + ac4 + 1] = f2tf32(avA[i].y);
                Asn[(size_t)m * ASTR + ac4 + 2] = f2tf32(avA[i].z);
                Asn[(size_t)m * ASTR + ac4 + 3] = f2tf32(avA[i].w);
            }
            asm volatile("cp.async.wait_group 0;");
        }
        __syncthreads();
    }

    // epilogue: c0,c1 at (m,n),(m,n+1); c2,c3 at (m+8,n),(m+8,n+1)
    #pragma unroll
    for (int mt = 0; mt < 4; mt++) {
        #pragma unroll
        for (int nt = 0; nt < 4; nt++) {
            int m = m0 + wm + mt * 16 + grp;
            int n = n0 + wn + nt * 8 + 2 * tig;
            float2 v0 = make_float2(acc[mt][nt][0], acc[mt][nt][1]);
            float2 v1 = make_float2(acc[mt][nt][2], acc[mt][nt][3]);
            if (resid) {
                float2 r0 = *(const float2*)&resid[(size_t)m * ldc + n];
                float2 r1 = *(const float2*)&resid[(size_t)(m + 8) * ldc + n];
                v0.x += r0.x; v0.y += r0.y;
                v1.x += r1.x; v1.y += r1.y;
            }
            if (gelu_src) {
                float2 g0 = *(const float2*)&gelu_src[(size_t)m * ldc + n];
                float2 g1 = *(const float2*)&gelu_src[(size_t)(m + 8) * ldc + n];
                float t0 = tanhf(0.7978845608028654f * (g0.x + 0.044715f * g0.x * g0.x * g0.x));
                float t1 = tanhf(0.7978845608028654f * (g0.y + 0.044715f * g0.y * g0.y * g0.y));
                float t2 = tanhf(0.7978845608028654f * (g1.x + 0.044715f * g1.x * g1.x * g1.x));
                float t3 = tanhf(0.7978845608028654f * (g1.y + 0.044715f * g1.y * g1.y * g1.y));
                v0.x *= 0.5f * g0.x * (1.f + t0);
                v0.y *= 0.5f * g0.y * (1.f + t1);
                v1.x *= 0.5f * g1.x * (1.f + t2);
                v1.y *= 0.5f * g1.y * (1.f + t3);
            }
            *(float2*)&C[(size_t)m * ldc + n]       = v0;
            *(float2*)&C[(size_t)(m + 8) * ldc + n] = v1;
        }
    }
}

// ---------------- RoPE (in place) ----------------
__global__ void rope_kernel(float* __restrict__ x, const int* __restrict__ positions,
                            int heads, float outscale) {
    int row = blockIdx.x;   // b*T + t
    int h   = blockIdx.y;
    int i   = threadIdx.x;  // 0..63
    float pos = (float)positions[row];
    float ts = powf(10000.f, (float)i / 64.f);
    float ang = pos / ts;
    float s, c;
    sincosf(ang, &s, &c);
    float* p = x + ((size_t)row * heads + h) * HD;
    float x1 = p[i], x2 = p[i + 64];
    p[i]      = (x1 * c - x2 * s) * outscale;
    p[i + 64] = (x2 * c + x1 * s) * outscale;
}

// ---------------- Flash attention (causal, online softmax) ----------------
constexpr int BQ = 16;
constexpr int BKfa = 128;
constexpr int STP = 20;

__global__ __launch_bounds__(128) void flash_kernel(
    const float* __restrict__ q, const float* __restrict__ k,
    const float* __restrict__ v, float* __restrict__ enc) {

    int tq0 = blockIdx.x * BQ;
    int n   = blockIdx.y;
    int b   = blockIdx.z;
    int kvh = n / GG;
    int tid = threadIdx.x;

    float* Qt   = dynsmem;                 // [HD][BQ]
    float* Ks   = Qt + HD * BQ;            // [BKfa][HD+1]
    float* Vs   = Ks + BKfa * (HD + 1);    // [BKfa][HD+1]
    float* St   = Vs + BKfa * (HD + 1);    // [BKfa][STP]
    float* m_sm = St + BKfa * STP;
    float* l_sm = m_sm + BQ;
    float* a_sm = l_sm + BQ;

    for (int idx = tid; idx < BQ * HD; idx += 128) {
        int d = idx >> 4, qi = idx & 15;
        Qt[idx] = q[(((size_t)b * Tt + tq0 + qi) * NH + n) * HD + d];
    }
    if (tid < BQ) { m_sm[tid] = -1e30f; l_sm[tid] = 0.f; }

    float o[BQ];
    #pragma unroll
    for (int i = 0; i < BQ; i++) o[i] = 0.f;

    int ntiles = (tq0 + BQ + BKfa - 1) / BKfa;
    for (int kt = 0; kt < ntiles; kt++) {
        int s0 = kt * BKfa;
        __syncthreads();
        for (int idx = tid; idx < BKfa * HD; idx += 128) {
            int j = idx >> 7, d = idx & 127;
            size_t g = (((size_t)b * Tt + s0 + j) * KHn + kvh) * HD + d;
            Ks[j * (HD + 1) + d] = k[g];
            Vs[j * (HD + 1) + d] = v[g];
        }
        __syncthreads();

        int j = tid;
        int s = s0 + j;
        float sc[BQ];
        #pragma unroll
        for (int qi = 0; qi < BQ; qi++) sc[qi] = 0.f;
        #pragma unroll 4
        for (int d = 0; d < HD; d++) {
            float kv_ = Ks[j * (HD + 1) + d];
            float qv[16];
            *(float4*)&qv[0]  = *(const float4*)&Qt[d * BQ + 0];
            *(float4*)&qv[4]  = *(const float4*)&Qt[d * BQ + 4];
            *(float4*)&qv[8]  = *(const float4*)&Qt[d * BQ + 8];
            *(float4*)&qv[12] = *(const float4*)&Qt[d * BQ + 12];
            #pragma unroll
            for (int qi = 0; qi < BQ; qi++) sc[qi] += qv[qi] * kv_;
        }
        #pragma unroll
        for (int qi = 0; qi < BQ; qi++)
            if (s > tq0 + qi) sc[qi] = -1e30f;

        #pragma unroll
        for (int qi = 0; qi < BQ; qi++) St[j * STP + qi] = sc[qi];
        __syncthreads();

        if (tid < BQ) {
            float mold = m_sm[tid];
            float rowmax = -1e30f;
            for (int jj = 0; jj < BKfa; jj++)
                rowmax = fmaxf(rowmax, St[jj * STP + tid]);
            float mnew = fmaxf(mold, rowmax);
            a_sm[tid] = __expf(mold - mnew);
            m_sm[tid] = mnew;
        }
        __syncthreads();

        #pragma unroll
        for (int qi = 0; qi < BQ; qi++) {
            float p = __expf(sc[qi] - m_sm[qi]);
            St[j * STP + qi] = p;
        }
        __syncthreads();

        if (tid < BQ) {
            float rs = 0.f;
            for (int jj = 0; jj < BKfa; jj++) rs += St[jj * STP + tid];
            l_sm[tid] = l_sm[tid] * a_sm[tid] + rs;
        }

        float al[BQ];
        #pragma unroll
        for (int qi = 0; qi < BQ; qi++) { al[qi] = a_sm[qi]; o[qi] *= al[qi]; }
        #pragma unroll 4
        for (int jj = 0; jj < BKfa; jj++) {
            float vv = Vs[jj * (HD + 1) + tid];
            float pv[16];
            *(float4*)&pv[0]  = *(const float4*)&St[jj * STP + 0];
            *(float4*)&pv[4]  = *(const float4*)&St[jj * STP + 4];
            *(float4*)&pv[8]  = *(const float4*)&St[jj * STP + 8];
            *(float4*)&pv[12] = *(const float4*)&St[jj * STP + 12];
            #pragma unroll
            for (int qi = 0; qi < BQ; qi++) o[qi] += pv[qi] * vv;
        }
    }
    __syncthreads();
    #pragma unroll
    for (int qi = 0; qi < BQ; qi++)
        enc[(((size_t)b * Tt + tq0 + qi) * NH + n) * HD + tid] = o[qi] / l_sm[qi];
}

// ---------------- launch ----------------
extern "C" void kernel_launch(void* const* d_in, const int* in_sizes, int n_in,
                              void* d_out, int out_size) {
    const float* x        = (const float*)d_in[0];
    const int*   pos      = (const int*)  d_in[1];
    // d_in[2] attn_mask: causal, recomputed in-kernel
    const float* w_q      = (const float*)d_in[3];
    const float* w_kv     = (const float*)d_in[4];
    const float* w_av     = (const float*)d_in[5];
    const float* s_attn   = (const float*)d_in[6];
    const float* s_ffw    = (const float*)d_in[7];
    const float* w_gating = (const float*)d_in[8];
    const float* w_linear = (const float*)d_in[9];
    float* out = (float*)d_out;

    float *xn, *qp, *kp, *vp, *encp, *resp, *hp, *gatep;
    cudaGetSymbolAddress((void**)&xn,    g_xn);
    cudaGetSymbolAddress((void**)&qp,    g_q);
    cudaGetSymbolAddress((void**)&kp,    g_k);
    cudaGetSymbolAddress((void**)&vp,    g_v);
    cudaGetSymbolAddress((void**)&encp,  g_enc);
    cudaGetSymbolAddress((void**)&resp,  g_res);
    cudaGetSymbolAddress((void**)&hp,    g_h);
    cudaGetSymbolAddress((void**)&gatep, g_gate);

    int gemm_smem = (2 * BM * (BK + 4) + 2 * BK * (BN + 8)) * (int)sizeof(float);
    cudaFuncSetAttribute(gemm_tc_kernel, cudaFuncAttributeMaxDynamicSharedMemorySize, gemm_smem);

    // 1. pre-attn rmsnorm
    rmsnorm_kernel<<<Mtot, 256>>>(x, s_attn, xn);

    // 2. projections (per-head tensor-core GEMMs)
    dim3 gq(1, Mtot / BM, NH);
    gemm_tc_kernel<<<gq, 256, gemm_smem>>>(xn, w_q, nullptr, nullptr, qp, Dd, HD, NH * HD,
                                           (long long)Dd * HD, HD);
    dim3 gk(1, Mtot / BM, KHn);
    gemm_tc_kernel<<<gk, 256, gemm_smem>>>(xn, w_kv, nullptr, nullptr, kp, Dd, HD, KHn * HD,
                                           (long long)Dd * HD, HD);
    gemm_tc_kernel<<<gk, 256, gemm_smem>>>(xn, w_kv + (size_t)KHn * Dd * HD, nullptr, nullptr, vp,
                                           Dd, HD, KHn * HD, (long long)Dd * HD, HD);

    // 3. rope
    rope_kernel<<<dim3(Mtot, NH), 64>>>(qp, pos, NH, 0.08838834764831845f); // H^-0.5
    rope_kernel<<<dim3(Mtot, KHn), 64>>>(kp, pos, KHn, 1.f);

    // 4. flash attention
    int fa_smem_bytes = (HD * BQ + 2 * BKfa * (HD + 1) + BKfa * STP + 3 * BQ) * (int)sizeof(float);
    cudaFuncSetAttribute(flash_kernel, cudaFuncAttributeMaxDynamicSharedMemorySize, fa_smem_bytes);
    flash_kernel<<<dim3(Tt / BQ, NH, Bc), 128, fa_smem_bytes>>>(qp, kp, vp, encp);

    // 5. attn output proj + residual
    dim3 gav(Dd / BN, Mtot / BM, 1);
    gemm_tc_kernel<<<gav, 256, gemm_smem>>>(encp, w_av, x, nullptr, resp, NH * HD, Dd, Dd, 0, 0);

    // 6. pre-ffw rmsnorm
    rmsnorm_kernel<<<Mtot, 256>>>(resp, s_ffw, hp);

    // 7. gate GEMM, then up GEMM with fused gelu(gate)*up -> gatep
    dim3 gff(FF / BN, Mtot / BM, 1);
    gemm_tc_kernel<<<gff, 256, gemm_smem>>>(hp, w_gating, nullptr, nullptr, gatep, Dd, FF, FF, 0, 0);
    gemm_tc_kernel<<<gff, 256, gemm_smem>>>(hp, w_gating + (size_t)Dd * FF, nullptr, gatep, gatep,
                                            Dd, FF, FF, 0, 0);

    // 8. down proj + residual -> out
    dim3 gout(Dd / BN, Mtot / BM, 1);
    gemm_tc_kernel<<<gout, 256, gemm_smem>>>(gatep, w_linear, resp, nullptr, out, FF, Dd, Dd, 0, 0);
}

// round 6
// speedup vs baseline: 4.5350x; 1.2803x over previous
#include <cuda_runtime.h>
#include <math.h>
#include <stdint.h>

// Problem constants
constexpr int Bc  = 2;
constexpr int Tt  = 2048;
constexpr int Dd  = 2048;
constexpr int NH  = 16;   // query heads
constexpr int KHn = 8;    // kv heads
constexpr int HD  = 128;  // head dim
constexpr int FF  = 8192; // ffw dim
constexpr int Mtot = Bc * Tt;      // 4096
constexpr int GG  = NH / KHn;      // 2

// -------- scratch (static device globals; no allocations) --------
__device__ float g_xn  [(size_t)Mtot * Dd];
__device__ float g_q   [(size_t)Mtot * NH * HD];
__device__ float g_k   [(size_t)Mtot * KHn * HD];
__device__ float g_v   [(size_t)Mtot * KHn * HD];
__device__ float g_enc [(size_t)Mtot * NH * HD];
__device__ float g_res [(size_t)Mtot * Dd];
__device__ float g_h   [(size_t)Mtot * Dd];
__device__ float g_gate[(size_t)Mtot * FF];
// tf32-converted weights: wq | wkv | wav | wgating | wlinear
constexpr size_t WQ_OFF  = 0;
constexpr size_t WKV_OFF = WQ_OFF  + (size_t)NH * Dd * HD;          // 4194304
constexpr size_t WAV_OFF = WKV_OFF + (size_t)2 * KHn * Dd * HD;     // 8388608
constexpr size_t WG_OFF  = WAV_OFF + (size_t)NH * HD * Dd;          // 12582912
constexpr size_t WL_OFF  = WG_OFF  + (size_t)2 * Dd * FF;           // 46137344
constexpr size_t WTOT    = WL_OFF  + (size_t)FF * Dd;               // 62914560
__device__ float g_w[WTOT];

__device__ __forceinline__ uint32_t f2tf32(float f) {
    uint32_t r;
    asm("cvt.rna.tf32.f32 %0, %1;" : "=r"(r) : "f"(f));
    return r;
}
__device__ __forceinline__ float roundtf32(float f) {
    return __uint_as_float(f2tf32(f));
}

// ---------------- weight tf32 pre-round ----------------
__global__ void cvt_kernel(const float* __restrict__ src, float* __restrict__ dst, int n4) {
    int i = blockIdx.x * blockDim.x + threadIdx.x;
    if (i < n4) {
        float4 v = ((const float4*)src)[i];
        v.x = roundtf32(v.x); v.y = roundtf32(v.y);
        v.z = roundtf32(v.z); v.w = roundtf32(v.w);
        ((float4*)dst)[i] = v;
    }
}

// ---------------- RMSNorm (optionally tf32-rounded output) ----------------
__global__ void rmsnorm_kernel(const float* __restrict__ x,
                               const float* __restrict__ scale,
                               float* __restrict__ out, int roundOut) {
    int row = blockIdx.x;
    const float* xr = x + (size_t)row * Dd;
    float ss = 0.f;
    for (int i = threadIdx.x; i < Dd; i += blockDim.x) {
        float v = xr[i];
        ss += v * v;
    }
    __shared__ float red[32];
    #pragma unroll
    for (int o = 16; o; o >>= 1) ss += __shfl_xor_sync(0xffffffffu, ss, o);
    if ((threadIdx.x & 31) == 0) red[threadIdx.x >> 5] = ss;
    __syncthreads();
    if (threadIdx.x < 32) {
        float v = (threadIdx.x < (blockDim.x >> 5)) ? red[threadIdx.x] : 0.f;
        #pragma unroll
        for (int o = 16; o; o >>= 1) v += __shfl_xor_sync(0xffffffffu, v, o);
        if (threadIdx.x == 0) red[0] = v;
    }
    __syncthreads();
    float inv = rsqrtf(red[0] / (float)Dd + 1e-6f);
    float* outr = out + (size_t)row * Dd;
    for (int i = threadIdx.x; i < Dd; i += blockDim.x) {
        float v = xr[i] * inv * (1.f + scale[i]);
        outr[i] = roundOut ? roundtf32(v) : v;
    }
}

// ---------------- TF32 tensor-core GEMM (3-stage cp.async pipeline) ------
// Inputs A,B are already tf32-rounded fp32 bit patterns -> zero cvt in loop.
constexpr int BM = 128, BN = 128, BK = 32;
constexpr int ASTR = BK + 4;   // 36
constexpr int BSTR = BN + 8;   // 136
constexpr int STG  = 3;

__device__ __forceinline__ void mma_tf32(float& c0, float& c1, float& c2, float& c3,
                                         uint32_t a0, uint32_t a1, uint32_t a2, uint32_t a3,
                                         uint32_t b0, uint32_t b1) {
    asm volatile(
        "mma.sync.aligned.m16n8k8.row.col.f32.tf32.tf32.f32 "
        "{%0,%1,%2,%3}, {%4,%5,%6,%7}, {%8,%9}, {%0,%1,%2,%3};"
        : "+f"(c0), "+f"(c1), "+f"(c2), "+f"(c3)
        : "r"(a0), "r"(a1), "r"(a2), "r"(a3), "r"(b0), "r"(b1));
}

__device__ __forceinline__ void cp_async16(uint32_t smem_addr, const void* gptr) {
    asm volatile("cp.async.cg.shared.global [%0], [%1], 16;" :: "r"(smem_addr), "l"(gptr));
}

extern __shared__ float dynsmem[];

__global__ __launch_bounds__(256, 2) void gemm_tc_kernel(
    const float* __restrict__ A, const float* __restrict__ Bm,
    const float* __restrict__ resid, const float* __restrict__ gelu_src,
    float* __restrict__ C,
    int Kd, int ldb, int ldc,
    long long bHeadStride, int cHeadOff, int roundOut) {

    Bm += (size_t)blockIdx.z * (size_t)bHeadStride;
    C  += (size_t)blockIdx.z * (size_t)cHeadOff;

    float* AsF = dynsmem;                        // [STG][BM][ASTR]
    float* BsF = dynsmem + STG * BM * ASTR;      // [STG][BK][BSTR]

    int m0 = blockIdx.y * BM, n0 = blockIdx.x * BN;
    int tid  = threadIdx.x;
    int lane = tid & 31, warp = tid >> 5;
    int grp = lane >> 2, tig = lane & 3;
    int wm = (warp >> 2) * 64;
    int wn = (warp & 3) * 32;

    int ar  = tid >> 3;            // A row base (rows ar+32*i)
    int ac4 = (tid & 7) * 4;       // A k-col
    int bkr = tid >> 5;            // B k-row base (rows bkr+8*i)
    int bc4 = (tid & 31) * 4;      // B n-col

    float acc[4][4][4];
    #pragma unroll
    for (int mt = 0; mt < 4; mt++)
        #pragma unroll
        for (int nt = 0; nt < 4; nt++)
            #pragma unroll
            for (int r = 0; r < 4; r++) acc[mt][nt][r] = 0.f;

    int ntile = Kd / BK;

    auto issue_tile = [&](int t, int buf) {
        int k0 = t * BK;
        float* Asb = AsF + (size_t)buf * BM * ASTR;
        float* Bsb = BsF + (size_t)buf * BK * BSTR;
        #pragma unroll
        for (int i = 0; i < 4; i++) {
            int m = ar + 32 * i;
            uint32_t sa = (uint32_t)__cvta_generic_to_shared(&Asb[(size_t)m * ASTR + ac4]);
            cp_async16(sa, &A[(size_t)(m0 + m) * Kd + k0 + ac4]);
        }
        #pragma unroll
        for (int i = 0; i < 4; i++) {
            int kr = bkr + 8 * i;
            uint32_t sa = (uint32_t)__cvta_generic_to_shared(&Bsb[(size_t)kr * BSTR + bc4]);
            cp_async16(sa, &Bm[(size_t)(k0 + kr) * ldb + n0 + bc4]);
        }
    };

    // prologue: tiles 0 and 1 as two groups
    issue_tile(0, 0);
    asm volatile("cp.async.commit_group;");
    if (ntile > 1) issue_tile(1, 1);
    asm volatile("cp.async.commit_group;");
    asm volatile("cp.async.wait_group 1;");
    __syncthreads();

    for (int t = 0; t < ntile; t++) {
        int buf = t % STG;
        const uint32_t* Asb = (const uint32_t*)(AsF + (size_t)buf * BM * ASTR);
        const uint32_t* Bsb = (const uint32_t*)(BsF + (size_t)buf * BK * BSTR);

        if (t + 2 < ntile) issue_tile(t + 2, (t + 2) % STG);
        asm volatile("cp.async.commit_group;");

        #pragma unroll
        for (int kk = 0; kk < 4; kk++) {
            int k = kk * 8;
            uint32_t af[4][4], bf[4][2];
            #pragma unroll
            for (int mt = 0; mt < 4; mt++) {
                int row = wm + mt * 16 + grp;
                af[mt][0] = Asb[(size_t)(row    ) * ASTR + k + tig];
                af[mt][1] = Asb[(size_t)(row + 8) * ASTR + k + tig];
                af[mt][2] = Asb[(size_t)(row    ) * ASTR + k + tig + 4];
                af[mt][3] = Asb[(size_t)(row + 8) * ASTR + k + tig + 4];
            }
            #pragma unroll
            for (int nt = 0; nt < 4; nt++) {
                int col = wn + nt * 8 + grp;
                bf[nt][0] = Bsb[(size_t)(k + tig    ) * BSTR + col];
                bf[nt][1] = Bsb[(size_t)(k + tig + 4) * BSTR + col];
            }
            #pragma unroll
            for (int mt = 0; mt < 4; mt++)
                #pragma unroll
                for (int nt = 0; nt < 4; nt++)
                    mma_tf32(acc[mt][nt][0], acc[mt][nt][1], acc[mt][nt][2], acc[mt][nt][3],
                             af[mt][0], af[mt][1], af[mt][2], af[mt][3],
                             bf[nt][0], bf[nt][1]);
        }

        asm volatile("cp.async.wait_group 1;");
        __syncthreads();
    }

    // epilogue
    #pragma unroll
    for (int mt = 0; mt < 4; mt++) {
        #pragma unroll
        for (int nt = 0; nt < 4; nt++) {
            int m = m0 + wm + mt * 16 + grp;
            int n = n0 + wn + nt * 8 + 2 * tig;
            float2 v0 = make_float2(acc[mt][nt][0], acc[mt][nt][1]);
            float2 v1 = make_float2(acc[mt][nt][2], acc[mt][nt][3]);
            if (resid) {
                float2 r0 = *(const float2*)&resid[(size_t)m * ldc + n];
                float2 r1 = *(const float2*)&resid[(size_t)(m + 8) * ldc + n];
                v0.x += r0.x; v0.y += r0.y;
                v1.x += r1.x; v1.y += r1.y;
            }
            if (gelu_src) {
                float2 g0 = *(const float2*)&gelu_src[(size_t)m * ldc + n];
                float2 g1 = *(const float2*)&gelu_src[(size_t)(m + 8) * ldc + n];
                float t0 = tanhf(0.7978845608028654f * (g0.x + 0.044715f * g0.x * g0.x * g0.x));
                float t1 = tanhf(0.7978845608028654f * (g0.y + 0.044715f * g0.y * g0.y * g0.y));
                float t2 = tanhf(0.7978845608028654f * (g1.x + 0.044715f * g1.x * g1.x * g1.x));
                float t3 = tanhf(0.7978845608028654f * (g1.y + 0.044715f * g1.y * g1.y * g1.y));
                v0.x *= 0.5f * g0.x * (1.f + t0);
                v0.y *= 0.5f * g0.y * (1.f + t1);
                v1.x *= 0.5f * g1.x * (1.f + t2);
                v1.y *= 0.5f * g1.y * (1.f + t3);
            }
            if (roundOut) {
                v0.x = roundtf32(v0.x); v0.y = roundtf32(v0.y);
                v1.x = roundtf32(v1.x); v1.y = roundtf32(v1.y);
            }
            *(float2*)&C[(size_t)m * ldc + n]       = v0;
            *(float2*)&C[(size_t)(m + 8) * ldc + n] = v1;
        }
    }
}

// ---------------- RoPE (in place) ----------------
__global__ void rope_kernel(float* __restrict__ x, const int* __restrict__ positions,
                            int heads, float outscale) {
    int row = blockIdx.x;   // b*T + t
    int h   = blockIdx.y;
    int i   = threadIdx.x;  // 0..63
    float pos = (float)positions[row];
    float ts = powf(10000.f, (float)i / 64.f);
    float ang = pos / ts;
    float s, c;
    sincosf(ang, &s, &c);
    float* p = x + ((size_t)row * heads + h) * HD;
    float x1 = p[i], x2 = p[i + 64];
    p[i]      = (x1 * c - x2 * s) * outscale;
    p[i + 64] = (x2 * c + x1 * s) * outscale;
}

// ---------------- Flash attention (causal, online softmax, BK=64) --------
constexpr int BQ = 16;
constexpr int BKfa = 64;
constexpr int STP = 20;

__global__ __launch_bounds__(128, 2) void flash_kernel(
    const float* __restrict__ q, const float* __restrict__ k,
    const float* __restrict__ v, float* __restrict__ enc) {

    int tq0 = blockIdx.x * BQ;
    int n   = blockIdx.y;
    int b   = blockIdx.z;
    int kvh = n / GG;
    int tid = threadIdx.x;

    float* Qt   = dynsmem;                  // [HD][BQ]
    float* Ks   = Qt + HD * BQ;             // [BKfa][HD+1]
    float* Vs   = Ks + BKfa * (HD + 1);     // [BKfa][HD+1]
    float* St   = Vs + BKfa * (HD + 1);     // [BKfa][STP]
    float* m_sm = St + BKfa * STP;
    float* l_sm = m_sm + BQ;
    float* a_sm = l_sm + BQ;

    for (int idx = tid; idx < BQ * HD; idx += 128) {
        int d = idx >> 4, qi = idx & 15;
        Qt[idx] = q[(((size_t)b * Tt + tq0 + qi) * NH + n) * HD + d];
    }
    if (tid < BQ) { m_sm[tid] = -1e30f; l_sm[tid] = 0.f; }

    float o[BQ];
    #pragma unroll
    for (int i = 0; i < BQ; i++) o[i] = 0.f;

    int jloc = tid & 63;
    int qh   = tid >> 6;   // 0/1: query half

    int ntiles = (tq0 + BQ + BKfa - 1) / BKfa;
    for (int kt = 0; kt < ntiles; kt++) {
        int s0 = kt * BKfa;
        __syncthreads();
        for (int idx = tid; idx < BKfa * HD; idx += 128) {
            int j = idx >> 7, d = idx & 127;
            size_t g = (((size_t)b * Tt + s0 + j) * KHn + kvh) * HD + d;
            Ks[j * (HD + 1) + d] = k[g];
            Vs[j * (HD + 1) + d] = v[g];
        }
        __syncthreads();

        // scores: thread = (key jloc, query half qh) -> 8 queries each
        int s = s0 + jloc;
        float sc[8];
        #pragma unroll
        for (int i = 0; i < 8; i++) sc[i] = 0.f;
        #pragma unroll 4
        for (int d = 0; d < HD; d++) {
            float kv_ = Ks[jloc * (HD + 1) + d];
            float qv[8];
            *(float4*)&qv[0] = *(const float4*)&Qt[d * BQ + qh * 8];
            *(float4*)&qv[4] = *(const float4*)&Qt[d * BQ + qh * 8 + 4];
            #pragma unroll
            for (int i = 0; i < 8; i++) sc[i] += qv[i] * kv_;
        }
        #pragma unroll
        for (int i = 0; i < 8; i++)
            if (s > tq0 + qh * 8 + i) sc[i] = -1e30f;

        #pragma unroll
        for (int i = 0; i < 8; i++) St[jloc * STP + qh * 8 + i] = sc[i];
        __syncthreads();

        if (tid < BQ) {
            float mold = m_sm[tid];
            float rowmax = -1e30f;
            for (int jj = 0; jj < BKfa; jj++)
                rowmax = fmaxf(rowmax, St[jj * STP + tid]);
            float mnew = fmaxf(mold, rowmax);
            a_sm[tid] = __expf(mold - mnew);
            m_sm[tid] = mnew;
        }
        __syncthreads();

        #pragma unroll
        for (int i = 0; i < 8; i++) {
            float p = __expf(sc[i] - m_sm[qh * 8 + i]);
            St[jloc * STP + qh * 8 + i] = p;
        }
        __syncthreads();

        if (tid < BQ) {
            float rs = 0.f;
            for (int jj = 0; jj < BKfa; jj++) rs += St[jj * STP + tid];
            l_sm[tid] = l_sm[tid] * a_sm[tid] + rs;
        }

        // o update: thread = dim d (tid 0..127)
        #pragma unroll
        for (int qi = 0; qi < BQ; qi++) o[qi] *= a_sm[qi];
        #pragma unroll 4
        for (int jj = 0; jj < BKfa; jj++) {
            float vv = Vs[jj * (HD + 1) + tid];
            float pv[16];
            *(float4*)&pv[0]  = *(const float4*)&St[jj * STP + 0];
            *(float4*)&pv[4]  = *(const float4*)&St[jj * STP + 4];
            *(float4*)&pv[8]  = *(const float4*)&St[jj * STP + 8];
            *(float4*)&pv[12] = *(const float4*)&St[jj * STP + 12];
            #pragma unroll
            for (int qi = 0; qi < BQ; qi++) o[qi] += pv[qi] * vv;
        }
    }
    __syncthreads();
    #pragma unroll
    for (int qi = 0; qi < BQ; qi++)
        enc[(((size_t)b * Tt + tq0 + qi) * NH + n) * HD + tid] = roundtf32(o[qi] / l_sm[qi]);
}

// ---------------- launch ----------------
extern "C" void kernel_launch(void* const* d_in, const int* in_sizes, int n_in,
                              void* d_out, int out_size) {
    const float* x        = (const float*)d_in[0];
    const int*   pos      = (const int*)  d_in[1];
    // d_in[2] attn_mask: causal, recomputed in-kernel
    const float* w_q      = (const float*)d_in[3];
    const float* w_kv     = (const float*)d_in[4];
    const float* w_av     = (const float*)d_in[5];
    const float* s_attn   = (const float*)d_in[6];
    const float* s_ffw    = (const float*)d_in[7];
    const float* w_gating = (const float*)d_in[8];
    const float* w_linear = (const float*)d_in[9];
    float* out = (float*)d_out;

    float *xn, *qp, *kp, *vp, *encp, *resp, *hp, *gatep, *wc;
    cudaGetSymbolAddress((void**)&xn,    g_xn);
    cudaGetSymbolAddress((void**)&qp,    g_q);
    cudaGetSymbolAddress((void**)&kp,    g_k);
    cudaGetSymbolAddress((void**)&vp,    g_v);
    cudaGetSymbolAddress((void**)&encp,  g_enc);
    cudaGetSymbolAddress((void**)&resp,  g_res);
    cudaGetSymbolAddress((void**)&hp,    g_h);
    cudaGetSymbolAddress((void**)&gatep, g_gate);
    cudaGetSymbolAddress((void**)&wc,    g_w);

    int gemm_smem = (STG * BM * ASTR + STG * BK * BSTR) * (int)sizeof(float);
    cudaFuncSetAttribute(gemm_tc_kernel, cudaFuncAttributeMaxDynamicSharedMemorySize, gemm_smem);

    // 0. pre-round weights to tf32
    auto cvt = [](const float* s, float* d, size_t n) {
        cvt_kernel<<<(unsigned)((n / 4 + 255) / 256), 256>>>(s, d, (int)(n / 4));
    };
    cvt(w_q,      wc + WQ_OFF,  (size_t)NH * Dd * HD);
    cvt(w_kv,     wc + WKV_OFF, (size_t)2 * KHn * Dd * HD);
    cvt(w_av,     wc + WAV_OFF, (size_t)NH * HD * Dd);
    cvt(w_gating, wc + WG_OFF,  (size_t)2 * Dd * FF);
    cvt(w_linear, wc + WL_OFF,  (size_t)FF * Dd);

    // 1. pre-attn rmsnorm (tf32-rounded out)
    rmsnorm_kernel<<<Mtot, 256>>>(x, s_attn, xn, 1);

    // 2. projections (per-head tensor-core GEMMs)
    dim3 gq(1, Mtot / BM, NH);
    gemm_tc_kernel<<<gq, 256, gemm_smem>>>(xn, wc + WQ_OFF, nullptr, nullptr, qp,
                                           Dd, HD, NH * HD, (long long)Dd * HD, HD, 0);
    dim3 gk(1, Mtot / BM, KHn);
    gemm_tc_kernel<<<gk, 256, gemm_smem>>>(xn, wc + WKV_OFF, nullptr, nullptr, kp,
                                           Dd, HD, KHn * HD, (long long)Dd * HD, HD, 0);
    gemm_tc_kernel<<<gk, 256, gemm_smem>>>(xn, wc + WKV_OFF + (size_t)KHn * Dd * HD,
                                           nullptr, nullptr, vp,
                                           Dd, HD, KHn * HD, (long long)Dd * HD, HD, 0);

    // 3. rope
    rope_kernel<<<dim3(Mtot, NH), 64>>>(qp, pos, NH, 0.08838834764831845f); // H^-0.5
    rope_kernel<<<dim3(Mtot, KHn), 64>>>(kp, pos, KHn, 1.f);

    // 4. flash attention (enc emitted tf32-rounded)
    int fa_smem = (HD * BQ + 2 * BKfa * (HD + 1) + BKfa * STP + 3 * BQ) * (int)sizeof(float);
    cudaFuncSetAttribute(flash_kernel, cudaFuncAttributeMaxDynamicSharedMemorySize, fa_smem);
    flash_kernel<<<dim3(Tt / BQ, NH, Bc), 128, fa_smem>>>(qp, kp, vp, encp);

    // 5. attn output proj + residual (full fp32 out)
    dim3 gav(Dd / BN, Mtot / BM, 1);
    gemm_tc_kernel<<<gav, 256, gemm_smem>>>(encp, wc + WAV_OFF, x, nullptr, resp,
                                            NH * HD, Dd, Dd, 0, 0, 0);

    // 6. pre-ffw rmsnorm (tf32-rounded out)
    rmsnorm_kernel<<<Mtot, 256>>>(resp, s_ffw, hp, 1);

    // 7. gate GEMM, then up GEMM with fused gelu(gate)*up -> gatep (rounded)
    dim3 gff(FF / BN, Mtot / BM, 1);
    gemm_tc_kernel<<<gff, 256, gemm_smem>>>(hp, wc + WG_OFF, nullptr, nullptr, gatep,
                                            Dd, FF, FF, 0, 0, 0);
    gemm_tc_kernel<<<gff, 256, gemm_smem>>>(hp, wc + WG_OFF + (size_t)Dd * FF,
                                            nullptr, gatep, gatep,
                                            Dd, FF, FF, 0, 0, 1);

    // 8. down proj + residual -> out
    dim3 gout(Dd / BN, Mtot / BM, 1);
    gemm_tc_kernel<<<gout, 256, gemm_smem>>>(gatep, wc + WL_OFF, resp, nullptr, out,
                                             FF, Dd, Dd, 0, 0, 0);
}

// round 7
// speedup vs baseline: 6.6766x; 1.4722x over previous
#include <cuda_runtime.h>
#include <math.h>
#include <stdint.h>

// Problem constants
constexpr int Bc  = 2;
constexpr int Tt  = 2048;
constexpr int Dd  = 2048;
constexpr int NH  = 16;   // query heads
constexpr int KHn = 8;    // kv heads
constexpr int HD  = 128;  // head dim
constexpr int FF  = 8192; // ffw dim
constexpr int Mtot = Bc * Tt;      // 4096
constexpr int GG  = NH / KHn;      // 2

// -------- scratch (static device globals; no allocations) --------
__device__ float g_xn  [(size_t)Mtot * Dd];
__device__ float g_q   [(size_t)Mtot * NH * HD];
__device__ float g_k   [(size_t)Mtot * KHn * HD];
__device__ float g_v   [(size_t)Mtot * KHn * HD];
__device__ float g_enc [(size_t)Mtot * NH * HD];
__device__ float g_res [(size_t)Mtot * Dd];
__device__ float g_h   [(size_t)Mtot * Dd];
__device__ float g_gate[(size_t)Mtot * FF];
// tf32-converted weights: wq | wkv | wav | wgating | wlinear
constexpr size_t WQ_OFF  = 0;
constexpr size_t WKV_OFF = WQ_OFF  + (size_t)NH * Dd * HD;
constexpr size_t WAV_OFF = WKV_OFF + (size_t)2 * KHn * Dd * HD;
constexpr size_t WG_OFF  = WAV_OFF + (size_t)NH * HD * Dd;
constexpr size_t WL_OFF  = WG_OFF  + (size_t)2 * Dd * FF;
constexpr size_t WTOT    = WL_OFF  + (size_t)FF * Dd;
__device__ float g_w[WTOT];

__device__ __forceinline__ uint32_t f2tf32(float f) {
    uint32_t r;
    asm("cvt.rna.tf32.f32 %0, %1;" : "=r"(r) : "f"(f));
    return r;
}
__device__ __forceinline__ float roundtf32(float f) {
    return __uint_as_float(f2tf32(f));
}

// ---------------- weight tf32 pre-round ----------------
__global__ void cvt_kernel(const float* __restrict__ src, float* __restrict__ dst, int n4) {
    int i = blockIdx.x * blockDim.x + threadIdx.x;
    if (i < n4) {
        float4 v = ((const float4*)src)[i];
        v.x = roundtf32(v.x); v.y = roundtf32(v.y);
        v.z = roundtf32(v.z); v.w = roundtf32(v.w);
        ((float4*)dst)[i] = v;
    }
}

// ---------------- RMSNorm (optionally tf32-rounded output) ----------------
__global__ void rmsnorm_kernel(const float* __restrict__ x,
                               const float* __restrict__ scale,
                               float* __restrict__ out, int roundOut) {
    int row = blockIdx.x;
    const float* xr = x + (size_t)row * Dd;
    float ss = 0.f;
    for (int i = threadIdx.x; i < Dd; i += blockDim.x) {
        float v = xr[i];
        ss += v * v;
    }
    __shared__ float red[32];
    #pragma unroll
    for (int o = 16; o; o >>= 1) ss += __shfl_xor_sync(0xffffffffu, ss, o);
    if ((threadIdx.x & 31) == 0) red[threadIdx.x >> 5] = ss;
    __syncthreads();
    if (threadIdx.x < 32) {
        float v = (threadIdx.x < (blockDim.x >> 5)) ? red[threadIdx.x] : 0.f;
        #pragma unroll
        for (int o = 16; o; o >>= 1) v += __shfl_xor_sync(0xffffffffu, v, o);
        if (threadIdx.x == 0) red[0] = v;
    }
    __syncthreads();
    float inv = rsqrtf(red[0] / (float)Dd + 1e-6f);
    float* outr = out + (size_t)row * Dd;
    for (int i = threadIdx.x; i < Dd; i += blockDim.x) {
        float v = xr[i] * inv * (1.f + scale[i]);
        outr[i] = roundOut ? roundtf32(v) : v;
    }
}

// ---------------- TF32 tensor-core GEMM (3-stage cp.async pipeline) ------
constexpr int BM = 128, BN = 128, BK = 32;
constexpr int ASTR = BK + 4;   // 36
constexpr int BSTR = BN + 8;   // 136
constexpr int STG  = 3;

__device__ __forceinline__ void mma_tf32(float& c0, float& c1, float& c2, float& c3,
                                         uint32_t a0, uint32_t a1, uint32_t a2, uint32_t a3,
                                         uint32_t b0, uint32_t b1) {
    asm volatile(
        "mma.sync.aligned.m16n8k8.row.col.f32.tf32.tf32.f32 "
        "{%0,%1,%2,%3}, {%4,%5,%6,%7}, {%8,%9}, {%0,%1,%2,%3};"
        : "+f"(c0), "+f"(c1), "+f"(c2), "+f"(c3)
        : "r"(a0), "r"(a1), "r"(a2), "r"(a3), "r"(b0), "r"(b1));
}

__device__ __forceinline__ void cp_async16(uint32_t smem_addr, const void* gptr) {
    asm volatile("cp.async.cg.shared.global [%0], [%1], 16;" :: "r"(smem_addr), "l"(gptr));
}

extern __shared__ float dynsmem[];

__global__ __launch_bounds__(256, 2) void gemm_tc_kernel(
    const float* __restrict__ A, const float* __restrict__ Bm,
    const float* __restrict__ resid, const float* __restrict__ gelu_src,
    float* __restrict__ C,
    int Kd, int ldb, int ldc,
    long long bHeadStride, int cHeadOff, int roundOut) {

    Bm += (size_t)blockIdx.z * (size_t)bHeadStride;
    C  += (size_t)blockIdx.z * (size_t)cHeadOff;

    float* AsF = dynsmem;                        // [STG][BM][ASTR]
    float* BsF = dynsmem + STG * BM * ASTR;      // [STG][BK][BSTR]

    int m0 = blockIdx.y * BM, n0 = blockIdx.x * BN;
    int tid  = threadIdx.x;
    int lane = tid & 31, warp = tid >> 5;
    int grp = lane >> 2, tig = lane & 3;
    int wm = (warp >> 2) * 64;
    int wn = (warp & 3) * 32;

    int ar  = tid >> 3;
    int ac4 = (tid & 7) * 4;
    int bkr = tid >> 5;
    int bc4 = (tid & 31) * 4;

    float acc[4][4][4];
    #pragma unroll
    for (int mt = 0; mt < 4; mt++)
        #pragma unroll
        for (int nt = 0; nt < 4; nt++)
            #pragma unroll
            for (int r = 0; r < 4; r++) acc[mt][nt][r] = 0.f;

    int ntile = Kd / BK;

    auto issue_tile = [&](int t, int buf) {
        int k0 = t * BK;
        float* Asb = AsF + (size_t)buf * BM * ASTR;
        float* Bsb = BsF + (size_t)buf * BK * BSTR;
        #pragma unroll
        for (int i = 0; i < 4; i++) {
            int m = ar + 32 * i;
            uint32_t sa = (uint32_t)__cvta_generic_to_shared(&Asb[(size_t)m * ASTR + ac4]);
            cp_async16(sa, &A[(size_t)(m0 + m) * Kd + k0 + ac4]);
        }
        #pragma unroll
        for (int i = 0; i < 4; i++) {
            int kr = bkr + 8 * i;
            uint32_t sa = (uint32_t)__cvta_generic_to_shared(&Bsb[(size_t)kr * BSTR + bc4]);
            cp_async16(sa, &Bm[(size_t)(k0 + kr) * ldb + n0 + bc4]);
        }
    };

    issue_tile(0, 0);
    asm volatile("cp.async.commit_group;");
    if (ntile > 1) issue_tile(1, 1);
    asm volatile("cp.async.commit_group;");
    asm volatile("cp.async.wait_group 1;");
    __syncthreads();

    for (int t = 0; t < ntile; t++) {
        int buf = t % STG;
        const uint32_t* Asb = (const uint32_t*)(AsF + (size_t)buf * BM * ASTR);
        const uint32_t* Bsb = (const uint32_t*)(BsF + (size_t)buf * BK * BSTR);

        if (t + 2 < ntile) issue_tile(t + 2, (t + 2) % STG);
        asm volatile("cp.async.commit_group;");

        #pragma unroll
        for (int kk = 0; kk < 4; kk++) {
            int k = kk * 8;
            uint32_t af[4][4], bf[4][2];
            #pragma unroll
            for (int mt = 0; mt < 4; mt++) {
                int row = wm + mt * 16 + grp;
                af[mt][0] = Asb[(size_t)(row    ) * ASTR + k + tig];
                af[mt][1] = Asb[(size_t)(row + 8) * ASTR + k + tig];
                af[mt][2] = Asb[(size_t)(row    ) * ASTR + k + tig + 4];
                af[mt][3] = Asb[(size_t)(row + 8) * ASTR + k + tig + 4];
            }
            #pragma unroll
            for (int nt = 0; nt < 4; nt++) {
                int col = wn + nt * 8 + grp;
                bf[nt][0] = Bsb[(size_t)(k + tig    ) * BSTR + col];
                bf[nt][1] = Bsb[(size_t)(k + tig + 4) * BSTR + col];
            }
            #pragma unroll
            for (int mt = 0; mt < 4; mt++)
                #pragma unroll
                for (int nt = 0; nt < 4; nt++)
                    mma_tf32(acc[mt][nt][0], acc[mt][nt][1], acc[mt][nt][2], acc[mt][nt][3],
                             af[mt][0], af[mt][1], af[mt][2], af[mt][3],
                             bf[nt][0], bf[nt][1]);
        }

        asm volatile("cp.async.wait_group 1;");
        __syncthreads();
    }

    #pragma unroll
    for (int mt = 0; mt < 4; mt++) {
        #pragma unroll
        for (int nt = 0; nt < 4; nt++) {
            int m = m0 + wm + mt * 16 + grp;
            int n = n0 + wn + nt * 8 + 2 * tig;
            float2 v0 = make_float2(acc[mt][nt][0], acc[mt][nt][1]);
            float2 v1 = make_float2(acc[mt][nt][2], acc[mt][nt][3]);
            if (resid) {
                float2 r0 = *(const float2*)&resid[(size_t)m * ldc + n];
                float2 r1 = *(const float2*)&resid[(size_t)(m + 8) * ldc + n];
                v0.x += r0.x; v0.y += r0.y;
                v1.x += r1.x; v1.y += r1.y;
            }
            if (gelu_src) {
                float2 g0 = *(const float2*)&gelu_src[(size_t)m * ldc + n];
                float2 g1 = *(const float2*)&gelu_src[(size_t)(m + 8) * ldc + n];
                float t0 = tanhf(0.7978845608028654f * (g0.x + 0.044715f * g0.x * g0.x * g0.x));
                float t1 = tanhf(0.7978845608028654f * (g0.y + 0.044715f * g0.y * g0.y * g0.y));
                float t2 = tanhf(0.7978845608028654f * (g1.x + 0.044715f * g1.x * g1.x * g1.x));
                float t3 = tanhf(0.7978845608028654f * (g1.y + 0.044715f * g1.y * g1.y * g1.y));
                v0.x *= 0.5f * g0.x * (1.f + t0);
                v0.y *= 0.5f * g0.y * (1.f + t1);
                v1.x *= 0.5f * g1.x * (1.f + t2);
                v1.y *= 0.5f * g1.y * (1.f + t3);
            }
            if (roundOut) {
                v0.x = roundtf32(v0.x); v0.y = roundtf32(v0.y);
                v1.x = roundtf32(v1.x); v1.y = roundtf32(v1.y);
            }
            *(float2*)&C[(size_t)m * ldc + n]       = v0;
            *(float2*)&C[(size_t)(m + 8) * ldc + n] = v1;
        }
    }
}

// ---------------- RoPE (in place, tf32-rounded output) ----------------
__global__ void rope_kernel(float* __restrict__ x, const int* __restrict__ positions,
                            int heads, float outscale) {
    int row = blockIdx.x;
    int h   = blockIdx.y;
    int i   = threadIdx.x;  // 0..63
    float pos = (float)positions[row];
    float ts = powf(10000.f, (float)i / 64.f);
    float ang = pos / ts;
    float s, c;
    sincosf(ang, &s, &c);
    float* p = x + ((size_t)row * heads + h) * HD;
    float x1 = p[i], x2 = p[i + 64];
    p[i]      = roundtf32((x1 * c - x2 * s) * outscale);
    p[i + 64] = roundtf32((x2 * c + x1 * s) * outscale);
}

// ---------------- Flash attention (tf32 tensor-core, causal) -------------
// Block: 128 threads = 4 warps. BQ=64 queries (16/warp), key tiles of 64.
constexpr int FBQ = 64, FBS = 64;
constexpr int KVSTR = HD + 8;   // 136: stride ≡ 8 mod 32 -> conflict-free frags
constexpr int PSTR  = FBS + 8;  // 72

__global__ __launch_bounds__(128, 1) void flash_tc_kernel(
    const float* __restrict__ q, const float* __restrict__ k,
    const float* __restrict__ v, float* __restrict__ enc) {

    int tq0 = blockIdx.x * FBQ;
    int n   = blockIdx.y;
    int b   = blockIdx.z;
    int kvh = n / GG;
    int tid  = threadIdx.x;
    int lane = tid & 31, warp = tid >> 5;
    int grp = lane >> 2, tig = lane & 3;
    int wq = warp * 16;

    float* Qs = dynsmem;                       // [FBQ][KVSTR]
    float* Ks = Qs + FBQ * KVSTR;              // [FBS][KVSTR]
    float* Vs = Ks + FBS * KVSTR;              // [FBS][KVSTR]
    float* Ps = Vs + FBS * KVSTR;              // [4][16][PSTR]
    float* Pw = Ps + warp * 16 * PSTR;

    // load Q tile (already tf32-rounded by rope)
    for (int i = tid; i < FBQ * (HD / 4); i += 128) {
        int row = i >> 5, c4 = (i & 31) * 4;
        float4 qv = *(const float4*)&q[(((size_t)b * Tt + tq0 + row) * NH + n) * HD + c4];
        *(float4*)&Qs[row * KVSTR + c4] = qv;
    }

    float m0v = -1e30f, m1v = -1e30f, l0 = 0.f, l1 = 0.f;
    float O[16][4];
    #pragma unroll
    for (int nt = 0; nt < 16; nt++)
        #pragma unroll
        for (int r = 0; r < 4; r++) O[nt][r] = 0.f;

    int ntiles = blockIdx.x + 1;
    for (int kt = 0; kt < ntiles; kt++) {
        int s0 = kt * FBS;
        __syncthreads();
        for (int i = tid; i < FBS * (HD / 4); i += 128) {
            int row = i >> 5, c4 = (i & 31) * 4;
            size_t g = (((size_t)b * Tt + s0 + row) * KHn + kvh) * HD + c4;
            *(float4*)&Ks[row * KVSTR + c4] = *(const float4*)&k[g];
            *(float4*)&Vs[row * KVSTR + c4] = *(const float4*)&v[g];
        }
        __syncthreads();

        // ---- S = Q K^T  (rows wq+grp / wq+grp+8, cols s0 + nt*8+2tig{,+1})
        float sc[8][4];
        #pragma unroll
        for (int nt = 0; nt < 8; nt++)
            #pragma unroll
            for (int r = 0; r < 4; r++) sc[nt][r] = 0.f;

        const uint32_t* QsU = (const uint32_t*)Qs;
        const uint32_t* KsU = (const uint32_t*)Ks;
        const uint32_t* VsU = (const uint32_t*)Vs;
        #pragma unroll
        for (int kk = 0; kk < 16; kk++) {
            int kd = kk * 8;
            uint32_t a0 = QsU[(wq + grp    ) * KVSTR + kd + tig];
            uint32_t a1 = QsU[(wq + grp + 8) * KVSTR + kd + tig];
            uint32_t a2 = QsU[(wq + grp    ) * KVSTR + kd + tig + 4];
            uint32_t a3 = QsU[(wq + grp + 8) * KVSTR + kd + tig + 4];
            #pragma unroll
            for (int nt = 0; nt < 8; nt++) {
                uint32_t b0 = KsU[(nt * 8 + grp) * KVSTR + kd + tig];
                uint32_t b1 = KsU[(nt * 8 + grp) * KVSTR + kd + tig + 4];
                mma_tf32(sc[nt][0], sc[nt][1], sc[nt][2], sc[nt][3],
                         a0, a1, a2, a3, b0, b1);
            }
        }

        // causal mask
        int q0 = tq0 + wq + grp, q1 = q0 + 8;
        #pragma unroll
        for (int nt = 0; nt < 8; nt++) {
            int s = s0 + nt * 8 + 2 * tig;
            if (s     > q0) sc[nt][0] = -1e30f;
            if (s + 1 > q0) sc[nt][1] = -1e30f;
            if (s     > q1) sc[nt][2] = -1e30f;
            if (s + 1 > q1) sc[nt][3] = -1e30f;
        }

        // row max (quad reduce)
        float r0 = -1e30f, r1 = -1e30f;
        #pragma unroll
        for (int nt = 0; nt < 8; nt++) {
            r0 = fmaxf(r0, fmaxf(sc[nt][0], sc[nt][1]));
            r1 = fmaxf(r1, fmaxf(sc[nt][2], sc[nt][3]));
        }
        #pragma unroll
        for (int off = 1; off <= 2; off <<= 1) {
            r0 = fmaxf(r0, __shfl_xor_sync(0xffffffffu, r0, off));
            r1 = fmaxf(r1, __shfl_xor_sync(0xffffffffu, r1, off));
        }
        float mn0 = fmaxf(m0v, r0), mn1 = fmaxf(m1v, r1);
        float al0 = __expf(m0v - mn0), al1 = __expf(m1v - mn1);
        m0v = mn0; m1v = mn1;

        // probs + row sum + store P (tf32) to warp-private smem
        float rs0 = 0.f, rs1 = 0.f;
        #pragma unroll
        for (int nt = 0; nt < 8; nt++) {
            float p0 = __expf(sc[nt][0] - m0v);
            float p1 = __expf(sc[nt][1] - m0v);
            float p2 = __expf(sc[nt][2] - m1v);
            float p3 = __expf(sc[nt][3] - m1v);
            rs0 += p0 + p1; rs1 += p2 + p3;
            int cidx = nt * 8 + 2 * tig;
            Pw[(grp    ) * PSTR + cidx]     = roundtf32(p0);
            Pw[(grp    ) * PSTR + cidx + 1] = roundtf32(p1);
            Pw[(grp + 8) * PSTR + cidx]     = roundtf32(p2);
            Pw[(grp + 8) * PSTR + cidx + 1] = roundtf32(p3);
        }
        #pragma unroll
        for (int off = 1; off <= 2; off <<= 1) {
            rs0 += __shfl_xor_sync(0xffffffffu, rs0, off);
            rs1 += __shfl_xor_sync(0xffffffffu, rs1, off);
        }
        l0 = l0 * al0 + rs0;
        l1 = l1 * al1 + rs1;

        // rescale O
        #pragma unroll
        for (int nt = 0; nt < 16; nt++) {
            O[nt][0] *= al0; O[nt][1] *= al0;
            O[nt][2] *= al1; O[nt][3] *= al1;
        }

        __syncwarp();
        // ---- O += P V  (k = s, 8 steps; n = d, 16 tiles)
        const uint32_t* PwU = (const uint32_t*)Pw;
        #pragma unroll
        for (int kk = 0; kk < 8; kk++) {
            int ks = kk * 8;
            uint32_t a0 = PwU[(grp    ) * PSTR + ks + tig];
            uint32_t a1 = PwU[(grp + 8) * PSTR + ks + tig];
            uint32_t a2 = PwU[(grp    ) * PSTR + ks + tig + 4];
            uint32_t a3 = PwU[(grp + 8) * PSTR + ks + tig + 4];
            #pragma unroll
            for (int nt = 0; nt < 16; nt++) {
                uint32_t b0 = VsU[(ks + tig    ) * KVSTR + nt * 8 + grp];
                uint32_t b1 = VsU[(ks + tig + 4) * KVSTR + nt * 8 + grp];
                mma_tf32(O[nt][0], O[nt][1], O[nt][2], O[nt][3],
                         a0, a1, a2, a3, b0, b1);
            }
        }
    }

    // write out: enc row q, col nt*8+2tig (tf32-rounded for next GEMM)
    float il0 = 1.f / l0, il1 = 1.f / l1;
    int qr0 = tq0 + wq + grp, qr1 = qr0 + 8;
    #pragma unroll
    for (int nt = 0; nt < 16; nt++) {
        int c = nt * 8 + 2 * tig;
        float* e0 = &g_enc[(((size_t)b * Tt + qr0) * NH + n) * HD + c];
        float* e1 = &g_enc[(((size_t)b * Tt + qr1) * NH + n) * HD + c];
        e0[0] = roundtf32(O[nt][0] * il0);
        e0[1] = roundtf32(O[nt][1] * il0);
        e1[0] = roundtf32(O[nt][2] * il1);
        e1[1] = roundtf32(O[nt][3] * il1);
    }
    (void)enc;
}

// ---------------- launch ----------------
extern "C" void kernel_launch(void* const* d_in, const int* in_sizes, int n_in,
                              void* d_out, int out_size) {
    const float* x        = (const float*)d_in[0];
    const int*   pos      = (const int*)  d_in[1];
    // d_in[2] attn_mask: causal, recomputed in-kernel
    const float* w_q      = (const float*)d_in[3];
    const float* w_kv     = (const float*)d_in[4];
    const float* w_av     = (const float*)d_in[5];
    const float* s_attn   = (const float*)d_in[6];
    const float* s_ffw    = (const float*)d_in[7];
    const float* w_gating = (const float*)d_in[8];
    const float* w_linear = (const float*)d_in[9];
    float* out = (float*)d_out;

    float *xn, *qp, *kp, *vp, *encp, *resp, *hp, *gatep, *wc;
    cudaGetSymbolAddress((void**)&xn,    g_xn);
    cudaGetSymbolAddress((void**)&qp,    g_q);
    cudaGetSymbolAddress((void**)&kp,    g_k);
    cudaGetSymbolAddress((void**)&vp,    g_v);
    cudaGetSymbolAddress((void**)&encp,  g_enc);
    cudaGetSymbolAddress((void**)&resp,  g_res);
    cudaGetSymbolAddress((void**)&hp,    g_h);
    cudaGetSymbolAddress((void**)&gatep, g_gate);
    cudaGetSymbolAddress((void**)&wc,    g_w);

    int gemm_smem = (STG * BM * ASTR + STG * BK * BSTR) * (int)sizeof(float);
    cudaFuncSetAttribute(gemm_tc_kernel, cudaFuncAttributeMaxDynamicSharedMemorySize, gemm_smem);

    // 0. pre-round weights to tf32
    auto cvt = [](const float* s, float* d, size_t n) {
        cvt_kernel<<<(unsigned)((n / 4 + 255) / 256), 256>>>(s, d, (int)(n / 4));
    };
    cvt(w_q,      wc + WQ_OFF,  (size_t)NH * Dd * HD);
    cvt(w_kv,     wc + WKV_OFF, (size_t)2 * KHn * Dd * HD);
    cvt(w_av,     wc + WAV_OFF, (size_t)NH * HD * Dd);
    cvt(w_gating, wc + WG_OFF,  (size_t)2 * Dd * FF);
    cvt(w_linear, wc + WL_OFF,  (size_t)FF * Dd);

    // 1. pre-attn rmsnorm (tf32-rounded out)
    rmsnorm_kernel<<<Mtot, 256>>>(x, s_attn, xn, 1);

    // 2. projections
    dim3 gq(1, Mtot / BM, NH);
    gemm_tc_kernel<<<gq, 256, gemm_smem>>>(xn, wc + WQ_OFF, nullptr, nullptr, qp,
                                           Dd, HD, NH * HD, (long long)Dd * HD, HD, 0);
    dim3 gk(1, Mtot / BM, KHn);
    gemm_tc_kernel<<<gk, 256, gemm_smem>>>(xn, wc + WKV_OFF, nullptr, nullptr, kp,
                                           Dd, HD, KHn * HD, (long long)Dd * HD, HD, 0);
    gemm_tc_kernel<<<gk, 256, gemm_smem>>>(xn, wc + WKV_OFF + (size_t)KHn * Dd * HD,
                                           nullptr, nullptr, vp,
                                           Dd, HD, KHn * HD, (long long)Dd * HD, HD, 1);

    // 3. rope (outputs tf32-rounded)
    rope_kernel<<<dim3(Mtot, NH), 64>>>(qp, pos, NH, 0.08838834764831845f); // H^-0.5
    rope_kernel<<<dim3(Mtot, KHn), 64>>>(kp, pos, KHn, 1.f);

    // 4. flash attention (tf32 tensor-core)
    int fa_smem = (FBQ * KVSTR + 2 * FBS * KVSTR + 4 * 16 * PSTR) * (int)sizeof(float);
    cudaFuncSetAttribute(flash_tc_kernel, cudaFuncAttributeMaxDynamicSharedMemorySize, fa_smem);
    flash_tc_kernel<<<dim3(Tt / FBQ, NH, Bc), 128, fa_smem>>>(qp, kp, vp, encp);

    // 5. attn output proj + residual (full fp32 out)
    dim3 gav(Dd / BN, Mtot / BM, 1);
    gemm_tc_kernel<<<gav, 256, gemm_smem>>>(encp, wc + WAV_OFF, x, nullptr, resp,
                                            NH * HD, Dd, Dd, 0, 0, 0);

    // 6. pre-ffw rmsnorm (tf32-rounded out)
    rmsnorm_kernel<<<Mtot, 256>>>(resp, s_ffw, hp, 1);

    // 7. gate GEMM, then up GEMM with fused gelu(gate)*up
    dim3 gff(FF / BN, Mtot / BM, 1);
    gemm_tc_kernel<<<gff, 256, gemm_smem>>>(hp, wc + WG_OFF, nullptr, nullptr, gatep,
                                            Dd, FF, FF, 0, 0, 0);
    gemm_tc_kernel<<<gff, 256, gemm_smem>>>(hp, wc + WG_OFF + (size_t)Dd * FF,
                                            nullptr, gatep, gatep,
                                            Dd, FF, FF, 0, 0, 1);

    // 8. down proj + residual -> out
    dim3 gout(Dd / BN, Mtot / BM, 1);
    gemm_tc_kernel<<<gout, 256, gemm_smem>>>(gatep, wc + WL_OFF, resp, nullptr, out,
                                             FF, Dd, Dd, 0, 0, 0);
}